// round 12
// baseline (speedup 1.0000x reference)
#include <cuda_runtime.h>
#include <cuda_bf16.h>
#include <cstdint>
#include <math.h>

#define BATCH 32
#define NN    1024
#define NTOT  (BATCH*NN)   // 32768
#define NE    262144
#define INF_DIM 8
#define H     128
#define FEAS  64
#define NMAT  13

// ------------------------- scratch (static device memory) -------------------
__device__ __align__(16) float g_h[NTOT*H];
__device__ __align__(16) float g_t[NTOT*H];
__device__ __align__(16) float g_agg[NTOT*H];
__device__ __align__(16) float g_pool[NTOT*H];
__device__ __align__(16) float g_gp[BATCH*H];
__device__ __align__(16) float g_gb[BATCH*H];
__device__ __align__(16) float g_stats[4*2*H];   // per-BN-layer raw sum/sumsq
__device__ __align__(16) int   g_cnt[NTOT];
__device__ __align__(16) int   g_off[NTOT];
__device__ __align__(16) int   g_cur[NTOT];
__device__ __align__(16) int   g_eidx[NE];
__device__ __align__(16) int   g_bsum[128];
__device__ __align__(16) int   g_boff[128];
// weight images: per mat, W^T hi [n][k] (16384 ushorts) then lo (16384)
__device__ __align__(128) unsigned short g_wt[NMAT*32768];

// ------------------------------ MMA helpers ----------------------------------
__device__ __forceinline__ uint32_t smem_u32(const void* p) {
    uint32_t a;
    asm("{ .reg .u64 t; cvta.to.shared.u64 t, %1; cvt.u32.u64 %0, t; }" : "=r"(a) : "l"(p));
    return a;
}
__device__ __forceinline__ void ldsm_x4(uint32_t& r0, uint32_t& r1, uint32_t& r2,
                                        uint32_t& r3, uint32_t addr) {
    asm volatile("ldmatrix.sync.aligned.m8n8.x4.shared.b16 {%0,%1,%2,%3}, [%4];"
                 : "=r"(r0), "=r"(r1), "=r"(r2), "=r"(r3) : "r"(addr));
}
__device__ __forceinline__ void mma16816(float* c, const uint32_t* a,
                                         uint32_t b0, uint32_t b1) {
    asm volatile("mma.sync.aligned.m16n8k16.row.col.f32.bf16.bf16.f32 "
        "{%0,%1,%2,%3}, {%4,%5,%6,%7}, {%8,%9}, {%0,%1,%2,%3};"
        : "+f"(c[0]), "+f"(c[1]), "+f"(c[2]), "+f"(c[3])
        : "r"(a[0]), "r"(a[1]), "r"(a[2]), "r"(a[3]), "r"(b0), "r"(b1));
}
__device__ __forceinline__ void split2(float2 e, uint32_t& hi, uint32_t& lo) {
    __nv_bfloat162 h = __floats2bfloat162_rn(e.x, e.y);
    float2 f = __bfloat1622float2(h);
    __nv_bfloat162 l = __floats2bfloat162_rn(e.x - f.x, e.y - f.y);
    hi = *(uint32_t*)&h;
    lo = *(uint32_t*)&l;
}

// ------------------------------- small utils --------------------------------
__global__ void zero_misc() {
    int i = blockIdx.x*256 + threadIdx.x;     // 128 blocks -> 32768 threads
    g_cnt[i] = 0;
    ((float2*)g_agg)[i*4]     = make_float2(0.f,0.f);   // zero first NTOT*8 floats
    ((float2*)g_agg)[i*4 + 1] = make_float2(0.f,0.f);
    ((float2*)g_agg)[i*4 + 2] = make_float2(0.f,0.f);
    ((float2*)g_agg)[i*4 + 3] = make_float2(0.f,0.f);
    if (i < BATCH*H) g_gp[i] = 0.f;
    if (i < 4*2*H)   g_stats[i] = 0.f;
}
__global__ void deg_count(const int* __restrict__ dst) {
    int e = blockIdx.x*256 + threadIdx.x;
    if (e < NE) atomicAdd(&g_cnt[dst[e]], 1);
}
// hierarchical scan: block sums -> scan of 128 -> block-local offsets
__global__ void scan1() {                    // 128 blocks x 256
    __shared__ int sh[256];
    int t = threadIdx.x;
    sh[t] = g_cnt[blockIdx.x*256 + t];
    __syncthreads();
    for (int off = 128; off; off >>= 1) {
        if (t < off) sh[t] += sh[t + off];
        __syncthreads();
    }
    if (t == 0) g_bsum[blockIdx.x] = sh[0];
}
__global__ void scan2() {                    // 1 block x 128: exclusive scan
    __shared__ int sh[128];
    int t = threadIdx.x;
    sh[t] = g_bsum[t];
    __syncthreads();
    for (int off = 1; off < 128; off <<= 1) {
        int v = (t >= off) ? sh[t - off] : 0;
        __syncthreads();
        sh[t] += v;
        __syncthreads();
    }
    g_boff[t] = (t > 0) ? sh[t - 1] : 0;
}
__global__ void scan3() {                    // 128 blocks x 256
    __shared__ int sh[256];
    int t = threadIdx.x;
    int i = blockIdx.x*256 + t;
    int c = g_cnt[i];
    sh[t] = c;
    __syncthreads();
    for (int off = 1; off < 256; off <<= 1) {
        int v = (t >= off) ? sh[t - off] : 0;
        __syncthreads();
        sh[t] += v;
        __syncthreads();
    }
    int o = g_boff[blockIdx.x] + sh[t] - c;  // exclusive
    g_off[i] = o;
    g_cur[i] = o;
}
__global__ void fill_csr(const int* __restrict__ src, const int* __restrict__ dst) {
    int e = blockIdx.x*256 + threadIdx.x;
    if (e < NE) {
        int p = atomicAdd(&g_cur[dst[e]], 1);
        g_eidx[p] = src[e];
    }
}

// --------------------------- layer-0 scatter (IN=8) --------------------------
__device__ __forceinline__ void red_add_v4(float* p, float4 v) {
    asm volatile("red.global.add.v4.f32 [%0], {%1,%2,%3,%4};"
                 :: "l"(p), "f"(v.x), "f"(v.y), "f"(v.z), "f"(v.w) : "memory");
}
__global__ void scatter8(const float* __restrict__ x,
                         const int* __restrict__ src, const int* __restrict__ dst) {
    int t = blockIdx.x*256 + threadIdx.x;
    if (t >= NE*2) return;
    int e = t >> 1, c = (t & 1) << 2;
    int s = src[e], d = dst[e];
    float4 v = *(const float4*)(x + (size_t)s*INF_DIM + c);
    red_add_v4(g_agg + (size_t)d*INF_DIM + c, v);
}

// --------------------- CSR gather: z = h + mean_j h_j  (H=128) ---------------
__global__ __launch_bounds__(256) void gather_z() {
    int gw   = (blockIdx.x*256 + threadIdx.x) >> 5;   // 0..32767 (dst row)
    int lane = threadIdx.x & 31;
    int beg = g_off[gw], cnt = g_cnt[gw];
    const float4* h4 = (const float4*)g_h;
    float4 acc = make_float4(0.f,0.f,0.f,0.f);
    for (int e = 0; e < cnt; e++) {
        int s = g_eidx[beg + e];
        float4 v = h4[(size_t)s*32 + lane];
        acc.x += v.x; acc.y += v.y; acc.z += v.z; acc.w += v.w;
    }
    float inv = 1.f / fmaxf((float)cnt, 1.f);
    float4 hv = h4[(size_t)gw*32 + lane];
    float4 z;
    z.x = fmaf(acc.x, inv, hv.x); z.y = fmaf(acc.y, inv, hv.y);
    z.z = fmaf(acc.z, inv, hv.z); z.w = fmaf(acc.w, inv, hv.w);
    ((float4*)g_agg)[(size_t)gw*32 + lane] = z;
}

// ------------------- weight prep: split bf16, W^T [n][k] ---------------------
__global__ void wprep(const float* __restrict__ gin0_w2, const float* __restrict__ gin_w1,
                      const float* __restrict__ gin_w2, const float* __restrict__ pol0_w1,
                      const float* __restrict__ pol0_w2, const float* __restrict__ pol_w1,
                      const float* __restrict__ pol_w2) {
    int mat = blockIdx.y;
    const float* W;
    if      (mat == 0)  W = gin0_w2;
    else if (mat < 4)   W = gin_w1 + (size_t)(mat-1)*H*H;
    else if (mat < 7)   W = gin_w2 + (size_t)(mat-4)*H*H;
    else if (mat == 7)  W = pol0_w1;                    // first 128 rows
    else if (mat == 8)  W = pol0_w2;
    else if (mat < 11)  W = pol_w1 + (size_t)(mat-9)*H*H;
    else                W = pol_w2 + (size_t)(mat-11)*H*H;
    int idx = blockIdx.x*256 + threadIdx.x;             // 0..16383
    int n = idx >> 7, k = idx & 127;
    float el = W[(size_t)k*H + n];                      // B[n][k] = W[k][n]
    __nv_bfloat16 hb = __float2bfloat16(el);
    __nv_bfloat16 lb = __float2bfloat16(el - __bfloat162float(hb));
    unsigned short* base = g_wt + (size_t)mat*32768;
    base[idx]         = *(unsigned short*)&hb;
    base[16384 + idx] = *(unsigned short*)&lb;
}

// ------------------- HMMA GEMM: C[N,128] = epi(A@W + bias) -------------------
// split-bf16: C = Ahi*Bhi + Ahi*Blo + Alo*Bhi  (fp32 accum)
// 256 threads, 8 warps = 4M x 2N over a 128x128 tile.  A direct from global
// into register fragments (R9 core — best measured).
// EPI: 0 none, 1 relu, 2 tanh.  BIASMODE: 0 vec bias, 1 per-batch g_gb.
// STATS: accumulate column sum/sumsq of output into stats buffer (for BN).
#define BSTRIDE 136
#define SM_GEMM (2*128*BSTRIDE*2 + 512 + 1024)

template<int EPI, int BIASMODE, int STATS>
__global__ __launch_bounds__(256) void gemm_tc(
    const float* __restrict__ A, const float* __restrict__ bias,
    const unsigned short* __restrict__ Bt, float* __restrict__ C,
    float* __restrict__ stats)
{
    extern __shared__ __align__(16) char smem[];
    __nv_bfloat16* sBhi = (__nv_bfloat16*)smem;
    __nv_bfloat16* sBlo = sBhi + 128*BSTRIDE;
    float* sBias = (float*)(sBlo + 128*BSTRIDE);
    float* sSum  = sBias + 128;
    float* sSq   = sSum + 128;

    int tid = threadIdx.x;
    int wid = tid >> 5, lane = tid & 31;
    int wm = wid & 3, wn = wid >> 2;       // 4 M-warps x 2 N-warps
    int m0 = blockIdx.x * 128;

    if (tid < 128) {
        sBias[tid] = (BIASMODE == 1) ? g_gb[(size_t)(blockIdx.x >> 3)*H + tid] : bias[tid];
        if (STATS) { sSum[tid] = 0.f; sSq[tid] = 0.f; }
    }
    // copy B hi+lo into padded smem
    {
        const uint4* Bg = (const uint4*)Bt;   // 4096 uint4 (hi 2048, lo 2048)
#pragma unroll
        for (int i = tid; i < 4096; i += 256) {
            int half = i >> 11;               // 0 hi, 1 lo
            int j = i & 2047;
            int row = j >> 4, c = j & 15;
            __nv_bfloat16* d = (half ? sBlo : sBhi) + row*BSTRIDE + c*8;
            *(uint4*)d = Bg[i];
        }
    }
    __syncthreads();

    float acc[2][8][4];
#pragma unroll
    for (int mt = 0; mt < 2; mt++)
#pragma unroll
        for (int nt = 0; nt < 8; nt++)
#pragma unroll
            for (int q = 0; q < 4; q++) acc[mt][nt][q] = 0.f;

    int rbase = m0 + wm*32 + (lane >> 2);
    int cbase = (lane & 3)*2;
    int g  = lane >> 3, lr = lane & 7;
    const __nv_bfloat16* lbase = (g & 2) ? sBlo : sBhi;
    int kofs = (g & 1)*8;

#pragma unroll
    for (int k = 0; k < 8; k++) {
        int k0 = k*16;
        uint32_t ahi[2][4], alo[2][4];
#pragma unroll
        for (int mt = 0; mt < 2; mt++) {
            const float* Ar0 = A + (size_t)(rbase + mt*16)*H + k0 + cbase;
            const float* Ar1 = Ar0 + 8*H;
            split2(*(const float2*)Ar0,       ahi[mt][0], alo[mt][0]);
            split2(*(const float2*)Ar1,       ahi[mt][1], alo[mt][1]);
            split2(*(const float2*)(Ar0 + 8), ahi[mt][2], alo[mt][2]);
            split2(*(const float2*)(Ar1 + 8), ahi[mt][3], alo[mt][3]);
        }
#pragma unroll
        for (int nt = 0; nt < 8; nt++) {
            int n0 = wn*64 + nt*8;
            uint32_t addr = smem_u32(lbase + (size_t)(n0 + lr)*BSTRIDE + k0 + kofs);
            uint32_t bh0, bh1, bl0, bl1;
            ldsm_x4(bh0, bh1, bl0, bl1, addr);
#pragma unroll
            for (int mt = 0; mt < 2; mt++) {
                mma16816(acc[mt][nt], ahi[mt], bh0, bh1);
                mma16816(acc[mt][nt], ahi[mt], bl0, bl1);
                mma16816(acc[mt][nt], alo[mt], bh0, bh1);
            }
        }
    }

    // epilogue: bias + activation, write fp32 (+ optional BN stats)
    float s0[8], s1[8], q0[8], q1[8];
    if (STATS) {
#pragma unroll
        for (int nt = 0; nt < 8; nt++) { s0[nt]=0.f; s1[nt]=0.f; q0[nt]=0.f; q1[nt]=0.f; }
    }
#pragma unroll
    for (int mt = 0; mt < 2; mt++) {
        int r0 = m0 + wm*32 + mt*16 + (lane >> 2);
#pragma unroll
        for (int nt = 0; nt < 8; nt++) {
            int col = wn*64 + nt*8 + (lane & 3)*2;
            float bx = sBias[col], by = sBias[col + 1];
            float v0 = acc[mt][nt][0] + bx, v1 = acc[mt][nt][1] + by;
            float v2 = acc[mt][nt][2] + bx, v3 = acc[mt][nt][3] + by;
            if (EPI == 1) {
                v0 = fmaxf(v0, 0.f); v1 = fmaxf(v1, 0.f);
                v2 = fmaxf(v2, 0.f); v3 = fmaxf(v3, 0.f);
            } else if (EPI == 2) {
                v0 = tanhf(v0); v1 = tanhf(v1);
                v2 = tanhf(v2); v3 = tanhf(v3);
            }
            if (STATS) {
                s0[nt] += v0 + v2;  s1[nt] += v1 + v3;
                q0[nt] = fmaf(v0, v0, fmaf(v2, v2, q0[nt]));
                q1[nt] = fmaf(v1, v1, fmaf(v3, v3, q1[nt]));
            }
            *(float2*)(C + (size_t)r0*H + col)       = make_float2(v0, v1);
            *(float2*)(C + (size_t)(r0 + 8)*H + col) = make_float2(v2, v3);
        }
    }
    if (STATS) {
#pragma unroll
        for (int nt = 0; nt < 8; nt++) {
#pragma unroll
            for (int off = 4; off < 32; off <<= 1) {
                s0[nt] += __shfl_xor_sync(0xffffffffu, s0[nt], off);
                s1[nt] += __shfl_xor_sync(0xffffffffu, s1[nt], off);
                q0[nt] += __shfl_xor_sync(0xffffffffu, q0[nt], off);
                q1[nt] += __shfl_xor_sync(0xffffffffu, q1[nt], off);
            }
            if (lane < 4) {
                int col = wn*64 + nt*8 + lane*2;
                atomicAdd(&sSum[col],     s0[nt]);
                atomicAdd(&sSum[col + 1], s1[nt]);
                atomicAdd(&sSq[col],      q0[nt]);
                atomicAdd(&sSq[col + 1],  q1[nt]);
            }
        }
        __syncthreads();
        if (tid < 128) {
            atomicAdd(&stats[tid],     sSum[tid]);
            atomicAdd(&stats[H + tid], sSq[tid]);
        }
    }
}

// layer-0 first linear: K = 8, z-fold, relu.  out -> g_t
__global__ __launch_bounds__(256) void gemm_l0(
    const float* __restrict__ x, const float* __restrict__ w1,
    const float* __restrict__ b1)
{
    __shared__ float sW[INF_DIM*H];
    __shared__ float sB[H];
    int tid = threadIdx.x;
    for (int i = tid; i < INF_DIM*H; i += 256) sW[i] = w1[i];
    if (tid < H) sB[tid] = b1[tid];
    __syncthreads();

    int t   = blockIdx.x*256 + tid;
    int row = t >> 5, cg = t & 31;
    float id = 1.f / fmaxf((float)g_cnt[row], 1.f);
    const float4* x4 = (const float4*)x;
    const float4* g4 = (const float4*)g_agg;
    float4 a0 = x4[(size_t)row*2],   a1 = x4[(size_t)row*2 + 1];
    float4 q0 = g4[(size_t)row*2],   q1 = g4[(size_t)row*2 + 1];
    float z[8] = { fmaf(q0.x,id,a0.x), fmaf(q0.y,id,a0.y), fmaf(q0.z,id,a0.z), fmaf(q0.w,id,a0.w),
                   fmaf(q1.x,id,a1.x), fmaf(q1.y,id,a1.y), fmaf(q1.z,id,a1.z), fmaf(q1.w,id,a1.w) };
    const float4* sW4 = (const float4*)sW;
    float4 acc = ((const float4*)sB)[cg];
#pragma unroll
    for (int k = 0; k < 8; k++) {
        float4 w = sW4[k*32 + cg];
        acc.x = fmaf(z[k], w.x, acc.x); acc.y = fmaf(z[k], w.y, acc.y);
        acc.z = fmaf(z[k], w.z, acc.z); acc.w = fmaf(z[k], w.w, acc.w);
    }
    acc.x = fmaxf(acc.x, 0.f); acc.y = fmaxf(acc.y, 0.f);
    acc.z = fmaxf(acc.z, 0.f); acc.w = fmaxf(acc.w, 0.f);
    ((float4*)g_t)[(size_t)row*32 + cg] = acc;
}

// ------------------------------ batch norm -----------------------------------
// normalize from raw sums (mu/iv computed inline), write g_h,
// accumulate node_pool and per-batch gpool
template<int FIRST>
__global__ __launch_bounds__(256) void bn_norm(
    const float* __restrict__ r, const float* __restrict__ stats,
    const float* __restrict__ gamma, const float* __restrict__ beta)
{
    __shared__ float sp[H];
    int tid = threadIdx.x;
    if (tid < H) sp[tid] = 0.f;
    __syncthreads();

    int idx = blockIdx.x*256 + tid;   // NTOT*32 float4s
    int cg  = idx & 31;
    float4 v  = ((const float4*)r)[idx];
    float4 s4 = ((const float4*)stats)[cg];
    float4 w4 = ((const float4*)(stats + H))[cg];
    const float invN = 1.0f/NTOT;
    float4 mu, iv;
    mu.x = s4.x*invN; mu.y = s4.y*invN; mu.z = s4.z*invN; mu.w = s4.w*invN;
    iv.x = rsqrtf(fmaf(-mu.x, mu.x, w4.x*invN) + 1e-5f);
    iv.y = rsqrtf(fmaf(-mu.y, mu.y, w4.y*invN) + 1e-5f);
    iv.z = rsqrtf(fmaf(-mu.z, mu.z, w4.z*invN) + 1e-5f);
    iv.w = rsqrtf(fmaf(-mu.w, mu.w, w4.w*invN) + 1e-5f);
    float4 ga = ((const float4*)gamma)[cg];
    float4 be = ((const float4*)beta)[cg];
    float4 c;
    c.x = fmaf((v.x - mu.x)*iv.x, ga.x, be.x);
    c.y = fmaf((v.y - mu.y)*iv.y, ga.y, be.y);
    c.z = fmaf((v.z - mu.z)*iv.z, ga.z, be.z);
    c.w = fmaf((v.w - mu.w)*iv.w, ga.w, be.w);
    ((float4*)g_h)[idx] = c;
    if (FIRST) {
        ((float4*)g_pool)[idx] = c;
    } else {
        float4 p = ((float4*)g_pool)[idx];
        p.x += c.x; p.y += c.y; p.z += c.z; p.w += c.w;
        ((float4*)g_pool)[idx] = p;
    }
    atomicAdd(&sp[cg*4 + 0], c.x);
    atomicAdd(&sp[cg*4 + 1], c.y);
    atomicAdd(&sp[cg*4 + 2], c.z);
    atomicAdd(&sp[cg*4 + 3], c.w);
    __syncthreads();
    if (tid < H) {
        int b = blockIdx.x >> 7;   // 128 blocks per batch (8 rows/block)
        atomicAdd(&g_gp[b*H + tid], sp[tid] * (1.0f/NN));
    }
}

// per-batch policy bias: gb[b] = gpool[b] @ pol0_w1[128:256,:] + pol0_b1
__global__ void gb_kernel(const float* __restrict__ w1, const float* __restrict__ b1) {
    int b = blockIdx.x, n = threadIdx.x;
    __shared__ float sg[H];
    sg[n] = g_gp[b*H + n];
    __syncthreads();
    float acc = b1[n];
#pragma unroll 8
    for (int k = 0; k < H; k++) acc = fmaf(sg[k], w1[(size_t)(H + k)*H + n], acc);
    g_gb[b*H + n] = acc;
}

// ---------------------- final: masked score + softmax ------------------------
__global__ void final_softmax(const int* __restrict__ mrows,
                              const int* __restrict__ mcols,
                              float* __restrict__ out)
{
    __shared__ int   srow[FEAS], scol[FEAS], sdup[FEAS];
    __shared__ float ss[FEAS];
    __shared__ float smx, ssum;
    int b = blockIdx.x, tid = threadIdx.x;
    if (tid < FEAS) {
        srow[tid] = mrows[b*FEAS + tid];
        scol[tid] = mcols[b*FEAS + tid];
    }
    __syncthreads();
    int lane = tid & 31, w = tid >> 5;
    for (int j = w; j < FEAS; j += 8) {
        const float* zr = g_h + (size_t)srow[j]*H;
        const float* zc = g_h + (size_t)(b*NN + scol[j])*H;
        float s = 0.f;
        for (int k = lane; k < H; k += 32) s = fmaf(zr[k], zc[k], s);
#pragma unroll
        for (int o = 16; o; o >>= 1) s += __shfl_xor_sync(0xffffffffu, s, o);
        if (lane == 0) ss[j] = s;
    }
    __syncthreads();
    if (tid < FEAS) {
        int dup = 0;
        for (int k = 0; k < tid; k++)
            if (srow[k] == srow[tid] && scol[k] == scol[tid]) dup = 1;
        sdup[tid] = dup;
    }
    __syncthreads();
    if (tid == 0) {
        float mx = -1e30f;
        for (int j = 0; j < FEAS; j++) if (!sdup[j] && ss[j] > mx) mx = ss[j];
        float sum = 0.f;
        for (int j = 0; j < FEAS; j++) if (!sdup[j]) sum += expf(ss[j] - mx);
        smx = mx; ssum = sum;
    }
    __syncthreads();
    if (tid < FEAS) {
        int rl = srow[tid] - b*NN;
        size_t o = (size_t)b*NN*NN + (size_t)rl*NN + scol[tid];
        out[o] = expf(ss[tid] - smx) / ssum;
    }
}

// ------------------------------- host driver ---------------------------------
extern "C" void kernel_launch(void* const* d_in, const int* in_sizes, int n_in,
                              void* d_out, int out_size)
{
    const float* x       = (const float*)d_in[0];
    const int*   ei      = (const int*)  d_in[1];
    const int*   mrows   = (const int*)  d_in[3];
    const int*   mcols   = (const int*)  d_in[4];
    const float* gin0_w1 = (const float*)d_in[5];
    const float* gin0_b1 = (const float*)d_in[6];
    const float* gin0_w2 = (const float*)d_in[7];
    const float* gin0_b2 = (const float*)d_in[8];
    const float* gin_w1  = (const float*)d_in[9];
    const float* gin_b1  = (const float*)d_in[10];
    const float* gin_w2  = (const float*)d_in[11];
    const float* gin_b2  = (const float*)d_in[12];
    const float* bn_g    = (const float*)d_in[13];
    const float* bn_b    = (const float*)d_in[14];
    const float* pol0_w1 = (const float*)d_in[15];
    const float* pol0_b1 = (const float*)d_in[16];
    const float* pol0_w2 = (const float*)d_in[17];
    const float* pol0_b2 = (const float*)d_in[18];
    const float* pol_w1  = (const float*)d_in[19];
    const float* pol_b1  = (const float*)d_in[20];
    const float* pol_w2  = (const float*)d_in[21];
    const float* pol_b2  = (const float*)d_in[22];
    float* out = (float*)d_out;

    const int* src = ei;
    const int* dst = ei + NE;

    float *p_h, *p_t, *p_agg, *p_pool, *p_stats;
    unsigned short* p_wt;
    cudaGetSymbolAddress((void**)&p_h,     g_h);
    cudaGetSymbolAddress((void**)&p_t,     g_t);
    cudaGetSymbolAddress((void**)&p_agg,   g_agg);
    cudaGetSymbolAddress((void**)&p_pool,  g_pool);
    cudaGetSymbolAddress((void**)&p_stats, g_stats);
    cudaGetSymbolAddress((void**)&p_wt,    g_wt);
    auto WT = [&](int m) { return p_wt + (size_t)m*32768; };
    auto ST = [&](int l) { return p_stats + (size_t)l*2*H; };

    cudaFuncSetAttribute(gemm_tc<1,0,0>, cudaFuncAttributeMaxDynamicSharedMemorySize, SM_GEMM);
    cudaFuncSetAttribute(gemm_tc<1,0,1>, cudaFuncAttributeMaxDynamicSharedMemorySize, SM_GEMM);
    cudaFuncSetAttribute(gemm_tc<0,0,0>, cudaFuncAttributeMaxDynamicSharedMemorySize, SM_GEMM);
    cudaFuncSetAttribute(gemm_tc<2,0,0>, cudaFuncAttributeMaxDynamicSharedMemorySize, SM_GEMM);
    cudaFuncSetAttribute(gemm_tc<2,1,0>, cudaFuncAttributeMaxDynamicSharedMemorySize, SM_GEMM);

    cudaMemsetAsync(d_out, 0, (size_t)out_size * sizeof(float), 0);

    wprep<<<dim3(64, NMAT), 256>>>(gin0_w2, gin_w1, gin_w2, pol0_w1, pol0_w2, pol_w1, pol_w2);
    zero_misc<<<NTOT/256, 256>>>();
    deg_count<<<NE/256, 256>>>(dst);
    scan1<<<128, 256>>>();
    scan2<<<1, 128>>>();
    scan3<<<128, 256>>>();
    fill_csr<<<NE/256, 256>>>(src, dst);

    // ---------------- GIN layer 0 (IN=8) ----------------
    scatter8 <<<NE*2/256, 256>>>(x, src, dst);
    gemm_l0  <<<NTOT*32/256, 256>>>(x, gin0_w1, gin0_b1);
    gemm_tc<1,0,1><<<NTOT/128, 256, SM_GEMM>>>(p_t, gin0_b2, WT(0), p_agg, ST(0));
    bn_norm<1><<<NTOT*32/256, 256>>>(p_agg, ST(0), bn_g, bn_b);

    // ---------------- GIN layers 1..3 ----------------
    for (int l = 0; l < 3; l++) {
        gather_z<<<NTOT*32/256, 256>>>();
        gemm_tc<1,0,0><<<NTOT/128, 256, SM_GEMM>>>(p_agg, gin_b1 + l*H, WT(1 + l), p_t, nullptr);
        gemm_tc<1,0,1><<<NTOT/128, 256, SM_GEMM>>>(p_t, gin_b2 + l*H, WT(4 + l), p_agg, ST(l + 1));
        bn_norm<0><<<NTOT*32/256, 256>>>(p_agg, ST(l + 1),
                                         bn_g + (size_t)(l+1)*H, bn_b + (size_t)(l+1)*H);
    }

    // ---------------- policy head ----------------
    gb_kernel<<<BATCH, 128>>>(pol0_w1, pol0_b1);
    gemm_tc<2,1,0><<<NTOT/128, 256, SM_GEMM>>>(p_pool, nullptr,    WT(7),  p_t,   nullptr);
    gemm_tc<0,0,0><<<NTOT/128, 256, SM_GEMM>>>(p_t,    pol0_b2,    WT(8),  p_h,   nullptr);
    gemm_tc<2,0,0><<<NTOT/128, 256, SM_GEMM>>>(p_h,    pol_b1,     WT(9),  p_t,   nullptr);
    gemm_tc<0,0,0><<<NTOT/128, 256, SM_GEMM>>>(p_t,    pol_b2,     WT(11), p_agg, nullptr);
    gemm_tc<2,0,0><<<NTOT/128, 256, SM_GEMM>>>(p_agg,  pol_b1 + H, WT(10), p_t,   nullptr);
    gemm_tc<0,0,0><<<NTOT/128, 256, SM_GEMM>>>(p_t,    pol_b2 + H, WT(12), p_h,   nullptr);

    // ---------------- masked score + softmax ----------------
    final_softmax<<<BATCH, 256>>>(mrows, mcols, out);
}

// round 13
// speedup vs baseline: 1.0773x; 1.0773x over previous
#include <cuda_runtime.h>
#include <cuda_bf16.h>
#include <cstdint>
#include <math.h>

#define BATCH 32
#define NN    1024
#define NTOT  (BATCH*NN)   // 32768
#define NE    262144
#define INF_DIM 8
#define H     128
#define FEAS  64
#define NMAT  13

// ------------------------- scratch (static device memory) -------------------
__device__ __align__(16) float g_h[NTOT*H];
__device__ __align__(16) float g_t[NTOT*H];
__device__ __align__(16) float g_agg[NTOT*H];
__device__ __align__(16) float g_pool[NTOT*H];
__device__ __align__(16) float g_gp[BATCH*H];
__device__ __align__(16) float g_gb[BATCH*H];
__device__ __align__(16) float g_stats[4*2*H];   // per-BN-layer raw sum/sumsq
__device__ __align__(16) int   g_cnt[NTOT];
__device__ __align__(16) int   g_off[NTOT];
__device__ __align__(16) int   g_cur[NTOT];
__device__ __align__(16) int   g_eidx[NE];
__device__ __align__(16) int   g_bsum[128];
__device__ __align__(16) int   g_boff[128];
// weight images: per mat, W^T hi [n][k] (16384 ushorts) then lo (16384)
__device__ __align__(128) unsigned short g_wt[NMAT*32768];

// ------------------------------ MMA helpers ----------------------------------
__device__ __forceinline__ uint32_t smem_u32(const void* p) {
    uint32_t a;
    asm("{ .reg .u64 t; cvta.to.shared.u64 t, %1; cvt.u32.u64 %0, t; }" : "=r"(a) : "l"(p));
    return a;
}
__device__ __forceinline__ void ldsm_x4(uint32_t& r0, uint32_t& r1, uint32_t& r2,
                                        uint32_t& r3, uint32_t addr) {
    asm volatile("ldmatrix.sync.aligned.m8n8.x4.shared.b16 {%0,%1,%2,%3}, [%4];"
                 : "=r"(r0), "=r"(r1), "=r"(r2), "=r"(r3) : "r"(addr));
}
__device__ __forceinline__ void mma16816(float* c, const uint32_t* a,
                                         uint32_t b0, uint32_t b1) {
    asm volatile("mma.sync.aligned.m16n8k16.row.col.f32.bf16.bf16.f32 "
        "{%0,%1,%2,%3}, {%4,%5,%6,%7}, {%8,%9}, {%0,%1,%2,%3};"
        : "+f"(c[0]), "+f"(c[1]), "+f"(c[2]), "+f"(c[3])
        : "r"(a[0]), "r"(a[1]), "r"(a[2]), "r"(a[3]), "r"(b0), "r"(b1));
}
__device__ __forceinline__ void split2(float2 e, uint32_t& hi, uint32_t& lo) {
    __nv_bfloat162 h = __floats2bfloat162_rn(e.x, e.y);
    float2 f = __bfloat1622float2(h);
    __nv_bfloat162 l = __floats2bfloat162_rn(e.x - f.x, e.y - f.y);
    hi = *(uint32_t*)&h;
    lo = *(uint32_t*)&l;
}

// ------------------------------- small utils --------------------------------
__global__ void zero_misc() {
    int i = blockIdx.x*256 + threadIdx.x;     // 128 blocks -> 32768 threads
    g_cnt[i] = 0;
    ((float2*)g_agg)[i*4]     = make_float2(0.f,0.f);   // zero first NTOT*8 floats
    ((float2*)g_agg)[i*4 + 1] = make_float2(0.f,0.f);
    ((float2*)g_agg)[i*4 + 2] = make_float2(0.f,0.f);
    ((float2*)g_agg)[i*4 + 3] = make_float2(0.f,0.f);
    if (i < BATCH*H) g_gp[i] = 0.f;
    if (i < 4*2*H)   g_stats[i] = 0.f;
}
__global__ void deg_count(const int* __restrict__ dst) {
    int e = blockIdx.x*256 + threadIdx.x;
    if (e < NE) atomicAdd(&g_cnt[dst[e]], 1);
}
// hierarchical scan: block sums -> scan of 128 -> block-local offsets
__global__ void scan1() {                    // 128 blocks x 256
    __shared__ int sh[256];
    int t = threadIdx.x;
    sh[t] = g_cnt[blockIdx.x*256 + t];
    __syncthreads();
    for (int off = 128; off; off >>= 1) {
        if (t < off) sh[t] += sh[t + off];
        __syncthreads();
    }
    if (t == 0) g_bsum[blockIdx.x] = sh[0];
}
__global__ void scan2() {                    // 1 block x 128: exclusive scan
    __shared__ int sh[128];
    int t = threadIdx.x;
    sh[t] = g_bsum[t];
    __syncthreads();
    for (int off = 1; off < 128; off <<= 1) {
        int v = (t >= off) ? sh[t - off] : 0;
        __syncthreads();
        sh[t] += v;
        __syncthreads();
    }
    g_boff[t] = (t > 0) ? sh[t - 1] : 0;
}
__global__ void scan3() {                    // 128 blocks x 256
    __shared__ int sh[256];
    int t = threadIdx.x;
    int i = blockIdx.x*256 + t;
    int c = g_cnt[i];
    sh[t] = c;
    __syncthreads();
    for (int off = 1; off < 256; off <<= 1) {
        int v = (t >= off) ? sh[t - off] : 0;
        __syncthreads();
        sh[t] += v;
        __syncthreads();
    }
    int o = g_boff[blockIdx.x] + sh[t] - c;  // exclusive
    g_off[i] = o;
    g_cur[i] = o;
}
__global__ void fill_csr(const int* __restrict__ src, const int* __restrict__ dst) {
    int e = blockIdx.x*256 + threadIdx.x;
    if (e < NE) {
        int p = atomicAdd(&g_cur[dst[e]], 1);
        g_eidx[p] = src[e];
    }
}

// --------------------------- layer-0 scatter (IN=8) --------------------------
__device__ __forceinline__ void red_add_v4(float* p, float4 v) {
    asm volatile("red.global.add.v4.f32 [%0], {%1,%2,%3,%4};"
                 :: "l"(p), "f"(v.x), "f"(v.y), "f"(v.z), "f"(v.w) : "memory");
}
__global__ void scatter8(const float* __restrict__ x,
                         const int* __restrict__ src, const int* __restrict__ dst) {
    int t = blockIdx.x*256 + threadIdx.x;
    if (t >= NE*2) return;
    int e = t >> 1, c = (t & 1) << 2;
    int s = src[e], d = dst[e];
    float4 v = *(const float4*)(x + (size_t)s*INF_DIM + c);
    red_add_v4(g_agg + (size_t)d*INF_DIM + c, v);
}

// ------- fused gather + inline BN: z = bn(raw_i) + mean_j bn(raw_j) ----------
// reads raw from g_agg, writes z to g_t; accumulates node_pool and gpool with
// this layer's normalized values.
template<int FIRST>
__global__ __launch_bounds__(256) void gather_bn(
    const float* __restrict__ raw, const float* __restrict__ stats,
    const float* __restrict__ gamma, const float* __restrict__ beta)
{
    __shared__ float sp[H];
    int tid = threadIdx.x;
    if (tid < H) sp[tid] = 0.f;
    __syncthreads();

    int gw   = (blockIdx.x*256 + tid) >> 5;   // dst row (8 rows per block)
    int lane = tid & 31;

    // per-lane BN affine: c = v*a + b2
    float4 s4 = ((const float4*)stats)[lane];
    float4 w4 = ((const float4*)(stats + H))[lane];
    const float invN = 1.0f/NTOT;
    float4 mu, iv;
    mu.x = s4.x*invN; mu.y = s4.y*invN; mu.z = s4.z*invN; mu.w = s4.w*invN;
    iv.x = rsqrtf(fmaf(-mu.x, mu.x, w4.x*invN) + 1e-5f);
    iv.y = rsqrtf(fmaf(-mu.y, mu.y, w4.y*invN) + 1e-5f);
    iv.z = rsqrtf(fmaf(-mu.z, mu.z, w4.z*invN) + 1e-5f);
    iv.w = rsqrtf(fmaf(-mu.w, mu.w, w4.w*invN) + 1e-5f);
    float4 ga = ((const float4*)gamma)[lane];
    float4 be = ((const float4*)beta)[lane];
    float4 a, b2;
    a.x = iv.x*ga.x; a.y = iv.y*ga.y; a.z = iv.z*ga.z; a.w = iv.w*ga.w;
    b2.x = fmaf(-mu.x, a.x, be.x); b2.y = fmaf(-mu.y, a.y, be.y);
    b2.z = fmaf(-mu.z, a.z, be.z); b2.w = fmaf(-mu.w, a.w, be.w);

    int beg = g_off[gw], cnt = g_cnt[gw];
    const float4* r4 = (const float4*)raw;
    float4 acc = make_float4(0.f,0.f,0.f,0.f);
    for (int e = 0; e < cnt; e++) {
        int s = g_eidx[beg + e];
        float4 v = r4[(size_t)s*32 + lane];
        acc.x += fmaf(v.x, a.x, b2.x); acc.y += fmaf(v.y, a.y, b2.y);
        acc.z += fmaf(v.z, a.z, b2.z); acc.w += fmaf(v.w, a.w, b2.w);
    }
    float inv = 1.f / fmaxf((float)cnt, 1.f);
    float4 hv = r4[(size_t)gw*32 + lane];
    float4 c;
    c.x = fmaf(hv.x, a.x, b2.x); c.y = fmaf(hv.y, a.y, b2.y);
    c.z = fmaf(hv.z, a.z, b2.z); c.w = fmaf(hv.w, a.w, b2.w);
    float4 z;
    z.x = fmaf(acc.x, inv, c.x); z.y = fmaf(acc.y, inv, c.y);
    z.z = fmaf(acc.z, inv, c.z); z.w = fmaf(acc.w, inv, c.w);
    ((float4*)g_t)[(size_t)gw*32 + lane] = z;

    // node_pool accumulation with this layer's normalized value
    float4 p;
    if (FIRST) {
        p = c;
    } else {
        p = ((float4*)g_pool)[(size_t)gw*32 + lane];
        p.x += c.x; p.y += c.y; p.z += c.z; p.w += c.w;
    }
    ((float4*)g_pool)[(size_t)gw*32 + lane] = p;

    atomicAdd(&sp[lane*4 + 0], c.x);
    atomicAdd(&sp[lane*4 + 1], c.y);
    atomicAdd(&sp[lane*4 + 2], c.z);
    atomicAdd(&sp[lane*4 + 3], c.w);
    __syncthreads();
    if (tid < H) {
        int b = blockIdx.x >> 7;   // 128 blocks per batch (8 rows/block)
        atomicAdd(&g_gp[b*H + tid], sp[tid] * (1.0f/NN));
    }
}

// ------------------- weight prep: split bf16, W^T [n][k] ---------------------
__global__ void wprep(const float* __restrict__ gin0_w2, const float* __restrict__ gin_w1,
                      const float* __restrict__ gin_w2, const float* __restrict__ pol0_w1,
                      const float* __restrict__ pol0_w2, const float* __restrict__ pol_w1,
                      const float* __restrict__ pol_w2) {
    int mat = blockIdx.y;
    const float* W;
    if      (mat == 0)  W = gin0_w2;
    else if (mat < 4)   W = gin_w1 + (size_t)(mat-1)*H*H;
    else if (mat < 7)   W = gin_w2 + (size_t)(mat-4)*H*H;
    else if (mat == 7)  W = pol0_w1;                    // first 128 rows
    else if (mat == 8)  W = pol0_w2;
    else if (mat < 11)  W = pol_w1 + (size_t)(mat-9)*H*H;
    else                W = pol_w2 + (size_t)(mat-11)*H*H;
    int idx = blockIdx.x*256 + threadIdx.x;             // 0..16383
    int n = idx >> 7, k = idx & 127;
    float el = W[(size_t)k*H + n];                      // B[n][k] = W[k][n]
    __nv_bfloat16 hb = __float2bfloat16(el);
    __nv_bfloat16 lb = __float2bfloat16(el - __bfloat162float(hb));
    unsigned short* base = g_wt + (size_t)mat*32768;
    base[idx]         = *(unsigned short*)&hb;
    base[16384 + idx] = *(unsigned short*)&lb;
}

// ------------------- HMMA GEMM: C[N,128] = epi(A@W + bias) -------------------
// split-bf16: C = Ahi*Bhi + Ahi*Blo + Alo*Bhi  (fp32 accum)
// 256 threads, 8 warps = 4M x 2N over a 128x128 tile.  A direct from global
// into register fragments (R9 core — best measured).
// EPI: 0 none, 1 relu, 2 tanh.  BIASMODE: 0 vec bias, 1 per-batch g_gb.
// STATS: accumulate column sum/sumsq of output into stats buffer (for BN).
#define BSTRIDE 136
#define SM_GEMM (2*128*BSTRIDE*2 + 512 + 1024)

template<int EPI, int BIASMODE, int STATS>
__global__ __launch_bounds__(256) void gemm_tc(
    const float* __restrict__ A, const float* __restrict__ bias,
    const unsigned short* __restrict__ Bt, float* __restrict__ C,
    float* __restrict__ stats)
{
    extern __shared__ __align__(16) char smem[];
    __nv_bfloat16* sBhi = (__nv_bfloat16*)smem;
    __nv_bfloat16* sBlo = sBhi + 128*BSTRIDE;
    float* sBias = (float*)(sBlo + 128*BSTRIDE);
    float* sSum  = sBias + 128;
    float* sSq   = sSum + 128;

    int tid = threadIdx.x;
    int wid = tid >> 5, lane = tid & 31;
    int wm = wid & 3, wn = wid >> 2;       // 4 M-warps x 2 N-warps
    int m0 = blockIdx.x * 128;

    if (tid < 128) {
        sBias[tid] = (BIASMODE == 1) ? g_gb[(size_t)(blockIdx.x >> 3)*H + tid] : bias[tid];
        if (STATS) { sSum[tid] = 0.f; sSq[tid] = 0.f; }
    }
    // copy B hi+lo into padded smem
    {
        const uint4* Bg = (const uint4*)Bt;   // 4096 uint4 (hi 2048, lo 2048)
#pragma unroll
        for (int i = tid; i < 4096; i += 256) {
            int half = i >> 11;               // 0 hi, 1 lo
            int j = i & 2047;
            int row = j >> 4, c = j & 15;
            __nv_bfloat16* d = (half ? sBlo : sBhi) + row*BSTRIDE + c*8;
            *(uint4*)d = Bg[i];
        }
    }
    __syncthreads();

    float acc[2][8][4];
#pragma unroll
    for (int mt = 0; mt < 2; mt++)
#pragma unroll
        for (int nt = 0; nt < 8; nt++)
#pragma unroll
            for (int q = 0; q < 4; q++) acc[mt][nt][q] = 0.f;

    int rbase = m0 + wm*32 + (lane >> 2);
    int cbase = (lane & 3)*2;
    int g  = lane >> 3, lr = lane & 7;
    const __nv_bfloat16* lbase = (g & 2) ? sBlo : sBhi;
    int kofs = (g & 1)*8;

#pragma unroll
    for (int k = 0; k < 8; k++) {
        int k0 = k*16;
        uint32_t ahi[2][4], alo[2][4];
#pragma unroll
        for (int mt = 0; mt < 2; mt++) {
            const float* Ar0 = A + (size_t)(rbase + mt*16)*H + k0 + cbase;
            const float* Ar1 = Ar0 + 8*H;
            split2(*(const float2*)Ar0,       ahi[mt][0], alo[mt][0]);
            split2(*(const float2*)Ar1,       ahi[mt][1], alo[mt][1]);
            split2(*(const float2*)(Ar0 + 8), ahi[mt][2], alo[mt][2]);
            split2(*(const float2*)(Ar1 + 8), ahi[mt][3], alo[mt][3]);
        }
#pragma unroll
        for (int nt = 0; nt < 8; nt++) {
            int n0 = wn*64 + nt*8;
            uint32_t addr = smem_u32(lbase + (size_t)(n0 + lr)*BSTRIDE + k0 + kofs);
            uint32_t bh0, bh1, bl0, bl1;
            ldsm_x4(bh0, bh1, bl0, bl1, addr);
#pragma unroll
            for (int mt = 0; mt < 2; mt++) {
                mma16816(acc[mt][nt], ahi[mt], bh0, bh1);
                mma16816(acc[mt][nt], ahi[mt], bl0, bl1);
                mma16816(acc[mt][nt], alo[mt], bh0, bh1);
            }
        }
    }

    // epilogue: bias + activation, write fp32 (+ optional BN stats)
    float s0[8], s1[8], q0[8], q1[8];
    if (STATS) {
#pragma unroll
        for (int nt = 0; nt < 8; nt++) { s0[nt]=0.f; s1[nt]=0.f; q0[nt]=0.f; q1[nt]=0.f; }
    }
#pragma unroll
    for (int mt = 0; mt < 2; mt++) {
        int r0 = m0 + wm*32 + mt*16 + (lane >> 2);
#pragma unroll
        for (int nt = 0; nt < 8; nt++) {
            int col = wn*64 + nt*8 + (lane & 3)*2;
            float bx = sBias[col], by = sBias[col + 1];
            float v0 = acc[mt][nt][0] + bx, v1 = acc[mt][nt][1] + by;
            float v2 = acc[mt][nt][2] + bx, v3 = acc[mt][nt][3] + by;
            if (EPI == 1) {
                v0 = fmaxf(v0, 0.f); v1 = fmaxf(v1, 0.f);
                v2 = fmaxf(v2, 0.f); v3 = fmaxf(v3, 0.f);
            } else if (EPI == 2) {
                v0 = tanhf(v0); v1 = tanhf(v1);
                v2 = tanhf(v2); v3 = tanhf(v3);
            }
            if (STATS) {
                s0[nt] += v0 + v2;  s1[nt] += v1 + v3;
                q0[nt] = fmaf(v0, v0, fmaf(v2, v2, q0[nt]));
                q1[nt] = fmaf(v1, v1, fmaf(v3, v3, q1[nt]));
            }
            *(float2*)(C + (size_t)r0*H + col)       = make_float2(v0, v1);
            *(float2*)(C + (size_t)(r0 + 8)*H + col) = make_float2(v2, v3);
        }
    }
    if (STATS) {
#pragma unroll
        for (int nt = 0; nt < 8; nt++) {
#pragma unroll
            for (int off = 4; off < 32; off <<= 1) {
                s0[nt] += __shfl_xor_sync(0xffffffffu, s0[nt], off);
                s1[nt] += __shfl_xor_sync(0xffffffffu, s1[nt], off);
                q0[nt] += __shfl_xor_sync(0xffffffffu, q0[nt], off);
                q1[nt] += __shfl_xor_sync(0xffffffffu, q1[nt], off);
            }
            if (lane < 4) {
                int col = wn*64 + nt*8 + lane*2;
                atomicAdd(&sSum[col],     s0[nt]);
                atomicAdd(&sSum[col + 1], s1[nt]);
                atomicAdd(&sSq[col],      q0[nt]);
                atomicAdd(&sSq[col + 1],  q1[nt]);
            }
        }
        __syncthreads();
        if (tid < 128) {
            atomicAdd(&stats[tid],     sSum[tid]);
            atomicAdd(&stats[H + tid], sSq[tid]);
        }
    }
}

// layer-0 first linear: K = 8, z-fold, relu.  out -> g_t
__global__ __launch_bounds__(256) void gemm_l0(
    const float* __restrict__ x, const float* __restrict__ w1,
    const float* __restrict__ b1)
{
    __shared__ float sW[INF_DIM*H];
    __shared__ float sB[H];
    int tid = threadIdx.x;
    for (int i = tid; i < INF_DIM*H; i += 256) sW[i] = w1[i];
    if (tid < H) sB[tid] = b1[tid];
    __syncthreads();

    int t   = blockIdx.x*256 + tid;
    int row = t >> 5, cg = t & 31;
    float id = 1.f / fmaxf((float)g_cnt[row], 1.f);
    const float4* x4 = (const float4*)x;
    const float4* g4 = (const float4*)g_agg;
    float4 a0 = x4[(size_t)row*2],   a1 = x4[(size_t)row*2 + 1];
    float4 q0 = g4[(size_t)row*2],   q1 = g4[(size_t)row*2 + 1];
    float z[8] = { fmaf(q0.x,id,a0.x), fmaf(q0.y,id,a0.y), fmaf(q0.z,id,a0.z), fmaf(q0.w,id,a0.w),
                   fmaf(q1.x,id,a1.x), fmaf(q1.y,id,a1.y), fmaf(q1.z,id,a1.z), fmaf(q1.w,id,a1.w) };
    const float4* sW4 = (const float4*)sW;
    float4 acc = ((const float4*)sB)[cg];
#pragma unroll
    for (int k = 0; k < 8; k++) {
        float4 w = sW4[k*32 + cg];
        acc.x = fmaf(z[k], w.x, acc.x); acc.y = fmaf(z[k], w.y, acc.y);
        acc.z = fmaf(z[k], w.z, acc.z); acc.w = fmaf(z[k], w.w, acc.w);
    }
    acc.x = fmaxf(acc.x, 0.f); acc.y = fmaxf(acc.y, 0.f);
    acc.z = fmaxf(acc.z, 0.f); acc.w = fmaxf(acc.w, 0.f);
    ((float4*)g_t)[(size_t)row*32 + cg] = acc;
}

// ------------------------------ batch norm (final layer) ----------------------
// normalize from raw sums, optionally write g_h, accumulate node_pool + gpool
template<int FIRST, int STORE>
__global__ __launch_bounds__(256) void bn_norm(
    const float* __restrict__ r, const float* __restrict__ stats,
    const float* __restrict__ gamma, const float* __restrict__ beta)
{
    __shared__ float sp[H];
    int tid = threadIdx.x;
    if (tid < H) sp[tid] = 0.f;
    __syncthreads();

    int idx = blockIdx.x*256 + tid;   // NTOT*32 float4s
    int cg  = idx & 31;
    float4 v  = ((const float4*)r)[idx];
    float4 s4 = ((const float4*)stats)[cg];
    float4 w4 = ((const float4*)(stats + H))[cg];
    const float invN = 1.0f/NTOT;
    float4 mu, iv;
    mu.x = s4.x*invN; mu.y = s4.y*invN; mu.z = s4.z*invN; mu.w = s4.w*invN;
    iv.x = rsqrtf(fmaf(-mu.x, mu.x, w4.x*invN) + 1e-5f);
    iv.y = rsqrtf(fmaf(-mu.y, mu.y, w4.y*invN) + 1e-5f);
    iv.z = rsqrtf(fmaf(-mu.z, mu.z, w4.z*invN) + 1e-5f);
    iv.w = rsqrtf(fmaf(-mu.w, mu.w, w4.w*invN) + 1e-5f);
    float4 ga = ((const float4*)gamma)[cg];
    float4 be = ((const float4*)beta)[cg];
    float4 c;
    c.x = fmaf((v.x - mu.x)*iv.x, ga.x, be.x);
    c.y = fmaf((v.y - mu.y)*iv.y, ga.y, be.y);
    c.z = fmaf((v.z - mu.z)*iv.z, ga.z, be.z);
    c.w = fmaf((v.w - mu.w)*iv.w, ga.w, be.w);
    if (STORE) ((float4*)g_h)[idx] = c;
    if (FIRST) {
        ((float4*)g_pool)[idx] = c;
    } else {
        float4 p = ((float4*)g_pool)[idx];
        p.x += c.x; p.y += c.y; p.z += c.z; p.w += c.w;
        ((float4*)g_pool)[idx] = p;
    }
    atomicAdd(&sp[cg*4 + 0], c.x);
    atomicAdd(&sp[cg*4 + 1], c.y);
    atomicAdd(&sp[cg*4 + 2], c.z);
    atomicAdd(&sp[cg*4 + 3], c.w);
    __syncthreads();
    if (tid < H) {
        int b = blockIdx.x >> 7;   // 128 blocks per batch (8 rows/block)
        atomicAdd(&g_gp[b*H + tid], sp[tid] * (1.0f/NN));
    }
}

// per-batch policy bias: gb[b] = gpool[b] @ pol0_w1[128:256,:] + pol0_b1
__global__ void gb_kernel(const float* __restrict__ w1, const float* __restrict__ b1) {
    int b = blockIdx.x, n = threadIdx.x;
    __shared__ float sg[H];
    sg[n] = g_gp[b*H + n];
    __syncthreads();
    float acc = b1[n];
#pragma unroll 8
    for (int k = 0; k < H; k++) acc = fmaf(sg[k], w1[(size_t)(H + k)*H + n], acc);
    g_gb[b*H + n] = acc;
}

// ---------------------- final: masked score + softmax ------------------------
__global__ void final_softmax(const int* __restrict__ mrows,
                              const int* __restrict__ mcols,
                              float* __restrict__ out)
{
    __shared__ int   srow[FEAS], scol[FEAS], sdup[FEAS];
    __shared__ float ss[FEAS];
    __shared__ float smx, ssum;
    int b = blockIdx.x, tid = threadIdx.x;
    if (tid < FEAS) {
        srow[tid] = mrows[b*FEAS + tid];
        scol[tid] = mcols[b*FEAS + tid];
    }
    __syncthreads();
    int lane = tid & 31, w = tid >> 5;
    for (int j = w; j < FEAS; j += 8) {
        const float* zr = g_h + (size_t)srow[j]*H;
        const float* zc = g_h + (size_t)(b*NN + scol[j])*H;
        float s = 0.f;
        for (int k = lane; k < H; k += 32) s = fmaf(zr[k], zc[k], s);
#pragma unroll
        for (int o = 16; o; o >>= 1) s += __shfl_xor_sync(0xffffffffu, s, o);
        if (lane == 0) ss[j] = s;
    }
    __syncthreads();
    if (tid < FEAS) {
        int dup = 0;
        for (int k = 0; k < tid; k++)
            if (srow[k] == srow[tid] && scol[k] == scol[tid]) dup = 1;
        sdup[tid] = dup;
    }
    __syncthreads();
    if (tid == 0) {
        float mx = -1e30f;
        for (int j = 0; j < FEAS; j++) if (!sdup[j] && ss[j] > mx) mx = ss[j];
        float sum = 0.f;
        for (int j = 0; j < FEAS; j++) if (!sdup[j]) sum += expf(ss[j] - mx);
        smx = mx; ssum = sum;
    }
    __syncthreads();
    if (tid < FEAS) {
        int rl = srow[tid] - b*NN;
        size_t o = (size_t)b*NN*NN + (size_t)rl*NN + scol[tid];
        out[o] = expf(ss[tid] - smx) / ssum;
    }
}

// ------------------------------- host driver ---------------------------------
extern "C" void kernel_launch(void* const* d_in, const int* in_sizes, int n_in,
                              void* d_out, int out_size)
{
    const float* x       = (const float*)d_in[0];
    const int*   ei      = (const int*)  d_in[1];
    const int*   mrows   = (const int*)  d_in[3];
    const int*   mcols   = (const int*)  d_in[4];
    const float* gin0_w1 = (const float*)d_in[5];
    const float* gin0_b1 = (const float*)d_in[6];
    const float* gin0_w2 = (const float*)d_in[7];
    const float* gin0_b2 = (const float*)d_in[8];
    const float* gin_w1  = (const float*)d_in[9];
    const float* gin_b1  = (const float*)d_in[10];
    const float* gin_w2  = (const float*)d_in[11];
    const float* gin_b2  = (const float*)d_in[12];
    const float* bn_g    = (const float*)d_in[13];
    const float* bn_b    = (const float*)d_in[14];
    const float* pol0_w1 = (const float*)d_in[15];
    const float* pol0_b1 = (const float*)d_in[16];
    const float* pol0_w2 = (const float*)d_in[17];
    const float* pol0_b2 = (const float*)d_in[18];
    const float* pol_w1  = (const float*)d_in[19];
    const float* pol_b1  = (const float*)d_in[20];
    const float* pol_w2  = (const float*)d_in[21];
    const float* pol_b2  = (const float*)d_in[22];
    float* out = (float*)d_out;

    const int* src = ei;
    const int* dst = ei + NE;

    float *p_h, *p_t, *p_agg, *p_pool, *p_stats;
    unsigned short* p_wt;
    cudaGetSymbolAddress((void**)&p_h,     g_h);
    cudaGetSymbolAddress((void**)&p_t,     g_t);
    cudaGetSymbolAddress((void**)&p_agg,   g_agg);
    cudaGetSymbolAddress((void**)&p_pool,  g_pool);
    cudaGetSymbolAddress((void**)&p_stats, g_stats);
    cudaGetSymbolAddress((void**)&p_wt,    g_wt);
    auto WT = [&](int m) { return p_wt + (size_t)m*32768; };
    auto ST = [&](int l) { return p_stats + (size_t)l*2*H; };

    cudaFuncSetAttribute(gemm_tc<1,0,0>, cudaFuncAttributeMaxDynamicSharedMemorySize, SM_GEMM);
    cudaFuncSetAttribute(gemm_tc<1,0,1>, cudaFuncAttributeMaxDynamicSharedMemorySize, SM_GEMM);
    cudaFuncSetAttribute(gemm_tc<0,0,0>, cudaFuncAttributeMaxDynamicSharedMemorySize, SM_GEMM);
    cudaFuncSetAttribute(gemm_tc<2,0,0>, cudaFuncAttributeMaxDynamicSharedMemorySize, SM_GEMM);
    cudaFuncSetAttribute(gemm_tc<2,1,0>, cudaFuncAttributeMaxDynamicSharedMemorySize, SM_GEMM);

    cudaMemsetAsync(d_out, 0, (size_t)out_size * sizeof(float), 0);

    wprep<<<dim3(64, NMAT), 256>>>(gin0_w2, gin_w1, gin_w2, pol0_w1, pol0_w2, pol_w1, pol_w2);
    zero_misc<<<NTOT/256, 256>>>();
    deg_count<<<NE/256, 256>>>(dst);
    scan1<<<128, 256>>>();
    scan2<<<1, 128>>>();
    scan3<<<128, 256>>>();
    fill_csr<<<NE/256, 256>>>(src, dst);

    // ---------------- GIN layer 0 (IN=8): raw0 -> g_agg ----------------
    scatter8 <<<NE*2/256, 256>>>(x, src, dst);
    gemm_l0  <<<NTOT*32/256, 256>>>(x, gin0_w1, gin0_b1);
    gemm_tc<1,0,1><<<NTOT/128, 256, SM_GEMM>>>(p_t, gin0_b2, WT(0), p_agg, ST(0));

    // ---------------- GIN layers 1..3 (fused gather+BN) ----------------
    // gather_bn: raw(g_agg) -> z(g_t);  gemm1: g_t -> g_h;  gemm2: g_h -> g_agg
    for (int l = 0; l < 3; l++) {
        if (l == 0)
            gather_bn<1><<<NTOT*32/256, 256>>>(p_agg, ST(0), bn_g, bn_b);
        else
            gather_bn<0><<<NTOT*32/256, 256>>>(p_agg, ST(l),
                                               bn_g + (size_t)l*H, bn_b + (size_t)l*H);
        gemm_tc<1,0,0><<<NTOT/128, 256, SM_GEMM>>>(p_t, gin_b1 + l*H, WT(1 + l), p_h, nullptr);
        gemm_tc<1,0,1><<<NTOT/128, 256, SM_GEMM>>>(p_h, gin_b2 + l*H, WT(4 + l), p_agg, ST(l + 1));
    }
    // final BN (layer 3): pool/gpool only; g_h store dead (policy overwrites it)
    bn_norm<0,0><<<NTOT*32/256, 256>>>(p_agg, ST(3), bn_g + (size_t)3*H, bn_b + (size_t)3*H);

    // ---------------- policy head ----------------
    gb_kernel<<<BATCH, 128>>>(pol0_w1, pol0_b1);
    gemm_tc<2,1,0><<<NTOT/128, 256, SM_GEMM>>>(p_pool, nullptr,    WT(7),  p_t,   nullptr);
    gemm_tc<0,0,0><<<NTOT/128, 256, SM_GEMM>>>(p_t,    pol0_b2,    WT(8),  p_h,   nullptr);
    gemm_tc<2,0,0><<<NTOT/128, 256, SM_GEMM>>>(p_h,    pol_b1,     WT(9),  p_t,   nullptr);
    gemm_tc<0,0,0><<<NTOT/128, 256, SM_GEMM>>>(p_t,    pol_b2,     WT(11), p_agg, nullptr);
    gemm_tc<2,0,0><<<NTOT/128, 256, SM_GEMM>>>(p_agg,  pol_b1 + H, WT(10), p_t,   nullptr);
    gemm_tc<0,0,0><<<NTOT/128, 256, SM_GEMM>>>(p_t,    pol_b2 + H, WT(12), p_h,   nullptr);

    // ---------------- masked score + softmax ----------------
    final_softmax<<<BATCH, 256>>>(mrows, mcols, out);
}

// round 14
// speedup vs baseline: 1.1732x; 1.0890x over previous
#include <cuda_runtime.h>
#include <cuda_bf16.h>
#include <cstdint>
#include <math.h>

#define BATCH 32
#define NN    1024
#define NTOT  (BATCH*NN)   // 32768
#define NE    262144
#define INF_DIM 8
#define H     128
#define FEAS  64
#define NMAT  13
#define NPOL  (BATCH*128)  // 4096 compact policy rows

// ------------------------- scratch (static device memory) -------------------
__device__ __align__(16) float g_h[NTOT*H];
__device__ __align__(16) float g_t[NTOT*H];
__device__ __align__(16) float g_agg[NTOT*H];
__device__ __align__(16) float g_pool[NTOT*H];
__device__ __align__(16) float g_gp[BATCH*H];
__device__ __align__(16) float g_gb[BATCH*H];
__device__ __align__(16) float g_stats[4*2*H];   // per-BN-layer raw sum/sumsq
__device__ __align__(16) int   g_cnt[NTOT];
__device__ __align__(16) int   g_off[NTOT];
__device__ __align__(16) int   g_cur[NTOT];
__device__ __align__(16) int   g_eidx[NE];
__device__ __align__(16) int   g_bsum[128];
__device__ __align__(16) int   g_boff[128];
// weight images: per mat, W^T hi [n][k] (16384 ushorts) then lo (16384)
__device__ __align__(128) unsigned short g_wt[NMAT*32768];

// ------------------------------ MMA helpers ----------------------------------
__device__ __forceinline__ uint32_t smem_u32(const void* p) {
    uint32_t a;
    asm("{ .reg .u64 t; cvta.to.shared.u64 t, %1; cvt.u32.u64 %0, t; }" : "=r"(a) : "l"(p));
    return a;
}
__device__ __forceinline__ void ldsm_x4(uint32_t& r0, uint32_t& r1, uint32_t& r2,
                                        uint32_t& r3, uint32_t addr) {
    asm volatile("ldmatrix.sync.aligned.m8n8.x4.shared.b16 {%0,%1,%2,%3}, [%4];"
                 : "=r"(r0), "=r"(r1), "=r"(r2), "=r"(r3) : "r"(addr));
}
__device__ __forceinline__ void mma16816(float* c, const uint32_t* a,
                                         uint32_t b0, uint32_t b1) {
    asm volatile("mma.sync.aligned.m16n8k16.row.col.f32.bf16.bf16.f32 "
        "{%0,%1,%2,%3}, {%4,%5,%6,%7}, {%8,%9}, {%0,%1,%2,%3};"
        : "+f"(c[0]), "+f"(c[1]), "+f"(c[2]), "+f"(c[3])
        : "r"(a[0]), "r"(a[1]), "r"(a[2]), "r"(a[3]), "r"(b0), "r"(b1));
}
__device__ __forceinline__ void split2(float2 e, uint32_t& hi, uint32_t& lo) {
    __nv_bfloat162 h = __floats2bfloat162_rn(e.x, e.y);
    float2 f = __bfloat1622float2(h);
    __nv_bfloat162 l = __floats2bfloat162_rn(e.x - f.x, e.y - f.y);
    hi = *(uint32_t*)&h;
    lo = *(uint32_t*)&l;
}

// ------------------------------- small utils --------------------------------
__global__ void zero_misc() {
    int i = blockIdx.x*256 + threadIdx.x;     // 128 blocks -> 32768 threads
    g_cnt[i] = 0;
    ((float2*)g_agg)[i*4]     = make_float2(0.f,0.f);   // zero first NTOT*8 floats
    ((float2*)g_agg)[i*4 + 1] = make_float2(0.f,0.f);
    ((float2*)g_agg)[i*4 + 2] = make_float2(0.f,0.f);
    ((float2*)g_agg)[i*4 + 3] = make_float2(0.f,0.f);
    if (i < BATCH*H) g_gp[i] = 0.f;
    if (i < 4*2*H)   g_stats[i] = 0.f;
}
__global__ void deg_count(const int* __restrict__ dst) {
    int e = blockIdx.x*256 + threadIdx.x;
    if (e < NE) atomicAdd(&g_cnt[dst[e]], 1);
}
// hierarchical scan: block sums -> scan of 128 -> block-local offsets
__global__ void scan1() {                    // 128 blocks x 256
    __shared__ int sh[256];
    int t = threadIdx.x;
    sh[t] = g_cnt[blockIdx.x*256 + t];
    __syncthreads();
    for (int off = 128; off; off >>= 1) {
        if (t < off) sh[t] += sh[t + off];
        __syncthreads();
    }
    if (t == 0) g_bsum[blockIdx.x] = sh[0];
}
__global__ void scan2() {                    // 1 block x 128: exclusive scan
    __shared__ int sh[128];
    int t = threadIdx.x;
    sh[t] = g_bsum[t];
    __syncthreads();
    for (int off = 1; off < 128; off <<= 1) {
        int v = (t >= off) ? sh[t - off] : 0;
        __syncthreads();
        sh[t] += v;
        __syncthreads();
    }
    g_boff[t] = (t > 0) ? sh[t - 1] : 0;
}
__global__ void scan3() {                    // 128 blocks x 256
    __shared__ int sh[256];
    int t = threadIdx.x;
    int i = blockIdx.x*256 + t;
    int c = g_cnt[i];
    sh[t] = c;
    __syncthreads();
    for (int off = 1; off < 256; off <<= 1) {
        int v = (t >= off) ? sh[t - off] : 0;
        __syncthreads();
        sh[t] += v;
        __syncthreads();
    }
    int o = g_boff[blockIdx.x] + sh[t] - c;  // exclusive
    g_off[i] = o;
    g_cur[i] = o;
}
__global__ void fill_csr(const int* __restrict__ src, const int* __restrict__ dst) {
    int e = blockIdx.x*256 + threadIdx.x;
    if (e < NE) {
        int p = atomicAdd(&g_cur[dst[e]], 1);
        g_eidx[p] = src[e];
    }
}

// --------------------------- layer-0 scatter (IN=8) --------------------------
__device__ __forceinline__ void red_add_v4(float* p, float4 v) {
    asm volatile("red.global.add.v4.f32 [%0], {%1,%2,%3,%4};"
                 :: "l"(p), "f"(v.x), "f"(v.y), "f"(v.z), "f"(v.w) : "memory");
}
__global__ void scatter8(const float* __restrict__ x,
                         const int* __restrict__ src, const int* __restrict__ dst) {
    int t = blockIdx.x*256 + threadIdx.x;
    if (t >= NE*2) return;
    int e = t >> 1, c = (t & 1) << 2;
    int s = src[e], d = dst[e];
    float4 v = *(const float4*)(x + (size_t)s*INF_DIM + c);
    red_add_v4(g_agg + (size_t)d*INF_DIM + c, v);
}

// ------- fused gather + inline BN: z = bn(raw_i) + mean_j bn(raw_j) ----------
template<int FIRST>
__global__ __launch_bounds__(256) void gather_bn(
    const float* __restrict__ raw, const float* __restrict__ stats,
    const float* __restrict__ gamma, const float* __restrict__ beta)
{
    __shared__ float sp[H];
    int tid = threadIdx.x;
    if (tid < H) sp[tid] = 0.f;
    __syncthreads();

    int gw   = (blockIdx.x*256 + tid) >> 5;   // dst row (8 rows per block)
    int lane = tid & 31;

    float4 s4 = ((const float4*)stats)[lane];
    float4 w4 = ((const float4*)(stats + H))[lane];
    const float invN = 1.0f/NTOT;
    float4 mu, iv;
    mu.x = s4.x*invN; mu.y = s4.y*invN; mu.z = s4.z*invN; mu.w = s4.w*invN;
    iv.x = rsqrtf(fmaf(-mu.x, mu.x, w4.x*invN) + 1e-5f);
    iv.y = rsqrtf(fmaf(-mu.y, mu.y, w4.y*invN) + 1e-5f);
    iv.z = rsqrtf(fmaf(-mu.z, mu.z, w4.z*invN) + 1e-5f);
    iv.w = rsqrtf(fmaf(-mu.w, mu.w, w4.w*invN) + 1e-5f);
    float4 ga = ((const float4*)gamma)[lane];
    float4 be = ((const float4*)beta)[lane];
    float4 a, b2;
    a.x = iv.x*ga.x; a.y = iv.y*ga.y; a.z = iv.z*ga.z; a.w = iv.w*ga.w;
    b2.x = fmaf(-mu.x, a.x, be.x); b2.y = fmaf(-mu.y, a.y, be.y);
    b2.z = fmaf(-mu.z, a.z, be.z); b2.w = fmaf(-mu.w, a.w, be.w);

    int beg = g_off[gw], cnt = g_cnt[gw];
    const float4* r4 = (const float4*)raw;
    float4 acc = make_float4(0.f,0.f,0.f,0.f);
    for (int e = 0; e < cnt; e++) {
        int s = g_eidx[beg + e];
        float4 v = r4[(size_t)s*32 + lane];
        acc.x += fmaf(v.x, a.x, b2.x); acc.y += fmaf(v.y, a.y, b2.y);
        acc.z += fmaf(v.z, a.z, b2.z); acc.w += fmaf(v.w, a.w, b2.w);
    }
    float inv = 1.f / fmaxf((float)cnt, 1.f);
    float4 hv = r4[(size_t)gw*32 + lane];
    float4 c;
    c.x = fmaf(hv.x, a.x, b2.x); c.y = fmaf(hv.y, a.y, b2.y);
    c.z = fmaf(hv.z, a.z, b2.z); c.w = fmaf(hv.w, a.w, b2.w);
    float4 z;
    z.x = fmaf(acc.x, inv, c.x); z.y = fmaf(acc.y, inv, c.y);
    z.z = fmaf(acc.z, inv, c.z); z.w = fmaf(acc.w, inv, c.w);
    ((float4*)g_t)[(size_t)gw*32 + lane] = z;

    float4 p;
    if (FIRST) {
        p = c;
    } else {
        p = ((float4*)g_pool)[(size_t)gw*32 + lane];
        p.x += c.x; p.y += c.y; p.z += c.z; p.w += c.w;
    }
    ((float4*)g_pool)[(size_t)gw*32 + lane] = p;

    atomicAdd(&sp[lane*4 + 0], c.x);
    atomicAdd(&sp[lane*4 + 1], c.y);
    atomicAdd(&sp[lane*4 + 2], c.z);
    atomicAdd(&sp[lane*4 + 3], c.w);
    __syncthreads();
    if (tid < H) {
        int b = blockIdx.x >> 7;   // 128 blocks per batch (8 rows/block)
        atomicAdd(&g_gp[b*H + tid], sp[tid] * (1.0f/NN));
    }
}

// ------------------- weight prep: split bf16, W^T [n][k] ---------------------
__global__ void wprep(const float* __restrict__ gin0_w2, const float* __restrict__ gin_w1,
                      const float* __restrict__ gin_w2, const float* __restrict__ pol0_w1,
                      const float* __restrict__ pol0_w2, const float* __restrict__ pol_w1,
                      const float* __restrict__ pol_w2) {
    int mat = blockIdx.y;
    const float* W;
    if      (mat == 0)  W = gin0_w2;
    else if (mat < 4)   W = gin_w1 + (size_t)(mat-1)*H*H;
    else if (mat < 7)   W = gin_w2 + (size_t)(mat-4)*H*H;
    else if (mat == 7)  W = pol0_w1;                    // first 128 rows
    else if (mat == 8)  W = pol0_w2;
    else if (mat < 11)  W = pol_w1 + (size_t)(mat-9)*H*H;
    else                W = pol_w2 + (size_t)(mat-11)*H*H;
    int idx = blockIdx.x*256 + threadIdx.x;             // 0..16383
    int n = idx >> 7, k = idx & 127;
    float el = W[(size_t)k*H + n];                      // B[n][k] = W[k][n]
    __nv_bfloat16 hb = __float2bfloat16(el);
    __nv_bfloat16 lb = __float2bfloat16(el - __bfloat162float(hb));
    unsigned short* base = g_wt + (size_t)mat*32768;
    base[idx]         = *(unsigned short*)&hb;
    base[16384 + idx] = *(unsigned short*)&lb;
}

// ------------------- HMMA GEMM: C[N,128] = epi(A@W + bias) -------------------
// split-bf16: C = Ahi*Bhi + Ahi*Blo + Alo*Bhi  (fp32 accum)
// 256 threads, 8 warps = 4M x 2N over a 128x128 tile (R9 core).
// EPI: 0 none, 1 relu, 2 tanh.
// BIASMODE: 0 vec bias, 1 g_gb[blockIdx>>3], 2 g_gb[blockIdx] (compact pol rows)
// STATS: accumulate column sum/sumsq of output into stats buffer (for BN).
#define BSTRIDE 136
#define SM_GEMM (2*128*BSTRIDE*2 + 512 + 1024)

template<int EPI, int BIASMODE, int STATS>
__global__ __launch_bounds__(256) void gemm_tc(
    const float* __restrict__ A, const float* __restrict__ bias,
    const unsigned short* __restrict__ Bt, float* __restrict__ C,
    float* __restrict__ stats)
{
    extern __shared__ __align__(16) char smem[];
    __nv_bfloat16* sBhi = (__nv_bfloat16*)smem;
    __nv_bfloat16* sBlo = sBhi + 128*BSTRIDE;
    float* sBias = (float*)(sBlo + 128*BSTRIDE);
    float* sSum  = sBias + 128;
    float* sSq   = sSum + 128;

    int tid = threadIdx.x;
    int wid = tid >> 5, lane = tid & 31;
    int wm = wid & 3, wn = wid >> 2;       // 4 M-warps x 2 N-warps
    int m0 = blockIdx.x * 128;

    if (tid < 128) {
        const float* bptr;
        if      (BIASMODE == 1) bptr = g_gb + (size_t)(blockIdx.x >> 3)*H;
        else if (BIASMODE == 2) bptr = g_gb + (size_t)blockIdx.x*H;
        else                    bptr = bias;
        sBias[tid] = bptr[tid];
        if (STATS) { sSum[tid] = 0.f; sSq[tid] = 0.f; }
    }
    // copy B hi+lo into padded smem
    {
        const uint4* Bg = (const uint4*)Bt;   // 4096 uint4 (hi 2048, lo 2048)
#pragma unroll
        for (int i = tid; i < 4096; i += 256) {
            int half = i >> 11;               // 0 hi, 1 lo
            int j = i & 2047;
            int row = j >> 4, c = j & 15;
            __nv_bfloat16* d = (half ? sBlo : sBhi) + row*BSTRIDE + c*8;
            *(uint4*)d = Bg[i];
        }
    }
    __syncthreads();

    float acc[2][8][4];
#pragma unroll
    for (int mt = 0; mt < 2; mt++)
#pragma unroll
        for (int nt = 0; nt < 8; nt++)
#pragma unroll
            for (int q = 0; q < 4; q++) acc[mt][nt][q] = 0.f;

    int rbase = m0 + wm*32 + (lane >> 2);
    int cbase = (lane & 3)*2;
    int g  = lane >> 3, lr = lane & 7;
    const __nv_bfloat16* lbase = (g & 2) ? sBlo : sBhi;
    int kofs = (g & 1)*8;

#pragma unroll
    for (int k = 0; k < 8; k++) {
        int k0 = k*16;
        uint32_t ahi[2][4], alo[2][4];
#pragma unroll
        for (int mt = 0; mt < 2; mt++) {
            const float* Ar0 = A + (size_t)(rbase + mt*16)*H + k0 + cbase;
            const float* Ar1 = Ar0 + 8*H;
            split2(*(const float2*)Ar0,       ahi[mt][0], alo[mt][0]);
            split2(*(const float2*)Ar1,       ahi[mt][1], alo[mt][1]);
            split2(*(const float2*)(Ar0 + 8), ahi[mt][2], alo[mt][2]);
            split2(*(const float2*)(Ar1 + 8), ahi[mt][3], alo[mt][3]);
        }
#pragma unroll
        for (int nt = 0; nt < 8; nt++) {
            int n0 = wn*64 + nt*8;
            uint32_t addr = smem_u32(lbase + (size_t)(n0 + lr)*BSTRIDE + k0 + kofs);
            uint32_t bh0, bh1, bl0, bl1;
            ldsm_x4(bh0, bh1, bl0, bl1, addr);
#pragma unroll
            for (int mt = 0; mt < 2; mt++) {
                mma16816(acc[mt][nt], ahi[mt], bh0, bh1);
                mma16816(acc[mt][nt], ahi[mt], bl0, bl1);
                mma16816(acc[mt][nt], alo[mt], bh0, bh1);
            }
        }
    }

    // epilogue: bias + activation, write fp32 (+ optional BN stats)
    float s0[8], s1[8], q0[8], q1[8];
    if (STATS) {
#pragma unroll
        for (int nt = 0; nt < 8; nt++) { s0[nt]=0.f; s1[nt]=0.f; q0[nt]=0.f; q1[nt]=0.f; }
    }
#pragma unroll
    for (int mt = 0; mt < 2; mt++) {
        int r0 = m0 + wm*32 + mt*16 + (lane >> 2);
#pragma unroll
        for (int nt = 0; nt < 8; nt++) {
            int col = wn*64 + nt*8 + (lane & 3)*2;
            float bx = sBias[col], by = sBias[col + 1];
            float v0 = acc[mt][nt][0] + bx, v1 = acc[mt][nt][1] + by;
            float v2 = acc[mt][nt][2] + bx, v3 = acc[mt][nt][3] + by;
            if (EPI == 1) {
                v0 = fmaxf(v0, 0.f); v1 = fmaxf(v1, 0.f);
                v2 = fmaxf(v2, 0.f); v3 = fmaxf(v3, 0.f);
            } else if (EPI == 2) {
                v0 = tanhf(v0); v1 = tanhf(v1);
                v2 = tanhf(v2); v3 = tanhf(v3);
            }
            if (STATS) {
                s0[nt] += v0 + v2;  s1[nt] += v1 + v3;
                q0[nt] = fmaf(v0, v0, fmaf(v2, v2, q0[nt]));
                q1[nt] = fmaf(v1, v1, fmaf(v3, v3, q1[nt]));
            }
            *(float2*)(C + (size_t)r0*H + col)       = make_float2(v0, v1);
            *(float2*)(C + (size_t)(r0 + 8)*H + col) = make_float2(v2, v3);
        }
    }
    if (STATS) {
#pragma unroll
        for (int nt = 0; nt < 8; nt++) {
#pragma unroll
            for (int off = 4; off < 32; off <<= 1) {
                s0[nt] += __shfl_xor_sync(0xffffffffu, s0[nt], off);
                s1[nt] += __shfl_xor_sync(0xffffffffu, s1[nt], off);
                q0[nt] += __shfl_xor_sync(0xffffffffu, q0[nt], off);
                q1[nt] += __shfl_xor_sync(0xffffffffu, q1[nt], off);
            }
            if (lane < 4) {
                int col = wn*64 + nt*8 + lane*2;
                atomicAdd(&sSum[col],     s0[nt]);
                atomicAdd(&sSum[col + 1], s1[nt]);
                atomicAdd(&sSq[col],      q0[nt]);
                atomicAdd(&sSq[col + 1],  q1[nt]);
            }
        }
        __syncthreads();
        if (tid < 128) {
            atomicAdd(&stats[tid],     sSum[tid]);
            atomicAdd(&stats[H + tid], sSq[tid]);
        }
    }
}

// layer-0 first linear: K = 8, z-fold, relu.  out -> g_t
__global__ __launch_bounds__(256) void gemm_l0(
    const float* __restrict__ x, const float* __restrict__ w1,
    const float* __restrict__ b1)
{
    __shared__ float sW[INF_DIM*H];
    __shared__ float sB[H];
    int tid = threadIdx.x;
    for (int i = tid; i < INF_DIM*H; i += 256) sW[i] = w1[i];
    if (tid < H) sB[tid] = b1[tid];
    __syncthreads();

    int t   = blockIdx.x*256 + tid;
    int row = t >> 5, cg = t & 31;
    float id = 1.f / fmaxf((float)g_cnt[row], 1.f);
    const float4* x4 = (const float4*)x;
    const float4* g4 = (const float4*)g_agg;
    float4 a0 = x4[(size_t)row*2],   a1 = x4[(size_t)row*2 + 1];
    float4 q0 = g4[(size_t)row*2],   q1 = g4[(size_t)row*2 + 1];
    float z[8] = { fmaf(q0.x,id,a0.x), fmaf(q0.y,id,a0.y), fmaf(q0.z,id,a0.z), fmaf(q0.w,id,a0.w),
                   fmaf(q1.x,id,a1.x), fmaf(q1.y,id,a1.y), fmaf(q1.z,id,a1.z), fmaf(q1.w,id,a1.w) };
    const float4* sW4 = (const float4*)sW;
    float4 acc = ((const float4*)sB)[cg];
#pragma unroll
    for (int k = 0; k < 8; k++) {
        float4 w = sW4[k*32 + cg];
        acc.x = fmaf(z[k], w.x, acc.x); acc.y = fmaf(z[k], w.y, acc.y);
        acc.z = fmaf(z[k], w.z, acc.z); acc.w = fmaf(z[k], w.w, acc.w);
    }
    acc.x = fmaxf(acc.x, 0.f); acc.y = fmaxf(acc.y, 0.f);
    acc.z = fmaxf(acc.z, 0.f); acc.w = fmaxf(acc.w, 0.f);
    ((float4*)g_t)[(size_t)row*32 + cg] = acc;
}

// ------------------------------ batch norm (final layer) ----------------------
template<int FIRST, int STORE>
__global__ __launch_bounds__(256) void bn_norm(
    const float* __restrict__ r, const float* __restrict__ stats,
    const float* __restrict__ gamma, const float* __restrict__ beta)
{
    __shared__ float sp[H];
    int tid = threadIdx.x;
    if (tid < H) sp[tid] = 0.f;
    __syncthreads();

    int idx = blockIdx.x*256 + tid;   // NTOT*32 float4s
    int cg  = idx & 31;
    float4 v  = ((const float4*)r)[idx];
    float4 s4 = ((const float4*)stats)[cg];
    float4 w4 = ((const float4*)(stats + H))[cg];
    const float invN = 1.0f/NTOT;
    float4 mu, iv;
    mu.x = s4.x*invN; mu.y = s4.y*invN; mu.z = s4.z*invN; mu.w = s4.w*invN;
    iv.x = rsqrtf(fmaf(-mu.x, mu.x, w4.x*invN) + 1e-5f);
    iv.y = rsqrtf(fmaf(-mu.y, mu.y, w4.y*invN) + 1e-5f);
    iv.z = rsqrtf(fmaf(-mu.z, mu.z, w4.z*invN) + 1e-5f);
    iv.w = rsqrtf(fmaf(-mu.w, mu.w, w4.w*invN) + 1e-5f);
    float4 ga = ((const float4*)gamma)[cg];
    float4 be = ((const float4*)beta)[cg];
    float4 c;
    c.x = fmaf((v.x - mu.x)*iv.x, ga.x, be.x);
    c.y = fmaf((v.y - mu.y)*iv.y, ga.y, be.y);
    c.z = fmaf((v.z - mu.z)*iv.z, ga.z, be.z);
    c.w = fmaf((v.w - mu.w)*iv.w, ga.w, be.w);
    if (STORE) ((float4*)g_h)[idx] = c;
    if (FIRST) {
        ((float4*)g_pool)[idx] = c;
    } else {
        float4 p = ((float4*)g_pool)[idx];
        p.x += c.x; p.y += c.y; p.z += c.z; p.w += c.w;
        ((float4*)g_pool)[idx] = p;
    }
    atomicAdd(&sp[cg*4 + 0], c.x);
    atomicAdd(&sp[cg*4 + 1], c.y);
    atomicAdd(&sp[cg*4 + 2], c.z);
    atomicAdd(&sp[cg*4 + 3], c.w);
    __syncthreads();
    if (tid < H) {
        int b = blockIdx.x >> 7;   // 128 blocks per batch (8 rows/block)
        atomicAdd(&g_gp[b*H + tid], sp[tid] * (1.0f/NN));
    }
}

// per-batch policy bias: gb[b] = gpool[b] @ pol0_w1[128:256,:] + pol0_b1
__global__ void gb_kernel(const float* __restrict__ w1, const float* __restrict__ b1) {
    int b = blockIdx.x, n = threadIdx.x;
    __shared__ float sg[H];
    sg[n] = g_gp[b*H + n];
    __syncthreads();
    float acc = b1[n];
#pragma unroll 8
    for (int k = 0; k < H; k++) acc = fmaf(sg[k], w1[(size_t)(H + k)*H + n], acc);
    g_gb[b*H + n] = acc;
}

// ------- compact policy rows: slot b*128+j <- pool[mask row or col row] ------
__global__ __launch_bounds__(256) void gather_pol(
    const int* __restrict__ mrows, const int* __restrict__ mcols)
{
    int s    = (blockIdx.x*256 + threadIdx.x) >> 5;   // 0..NPOL-1
    int lane = threadIdx.x & 31;
    int b = s >> 7, j = s & 127;
    int src = (j < FEAS) ? mrows[b*FEAS + j] : (b*NN + mcols[b*FEAS + j - FEAS]);
    float4 v = ((const float4*)g_pool)[(size_t)src*32 + lane];
    ((float4*)g_t)[(size_t)s*32 + lane] = v;
}

// ---------------------- final: masked score + softmax ------------------------
// z is compact: slot b*128+j = z at mask_rows[b,j]; slot b*128+64+j = z at col row
__global__ void final_softmax(const float* __restrict__ zc,
                              const int* __restrict__ mrows,
                              const int* __restrict__ mcols,
                              float* __restrict__ out)
{
    __shared__ int   srow[FEAS], scol[FEAS], sdup[FEAS];
    __shared__ float ss[FEAS];
    __shared__ float smx, ssum;
    int b = blockIdx.x, tid = threadIdx.x;
    if (tid < FEAS) {
        srow[tid] = mrows[b*FEAS + tid];
        scol[tid] = mcols[b*FEAS + tid];
    }
    __syncthreads();
    int lane = tid & 31, w = tid >> 5;
    for (int j = w; j < FEAS; j += 8) {
        const float* zr = zc + (size_t)(b*128 + j)*H;
        const float* zl = zc + (size_t)(b*128 + FEAS + j)*H;
        float s = 0.f;
        for (int k = lane; k < H; k += 32) s = fmaf(zr[k], zl[k], s);
#pragma unroll
        for (int o = 16; o; o >>= 1) s += __shfl_xor_sync(0xffffffffu, s, o);
        if (lane == 0) ss[j] = s;
    }
    __syncthreads();
    if (tid < FEAS) {
        int dup = 0;
        for (int k = 0; k < tid; k++)
            if (srow[k] == srow[tid] && scol[k] == scol[tid]) dup = 1;
        sdup[tid] = dup;
    }
    __syncthreads();
    if (tid == 0) {
        float mx = -1e30f;
        for (int j = 0; j < FEAS; j++) if (!sdup[j] && ss[j] > mx) mx = ss[j];
        float sum = 0.f;
        for (int j = 0; j < FEAS; j++) if (!sdup[j]) sum += expf(ss[j] - mx);
        smx = mx; ssum = sum;
    }
    __syncthreads();
    if (tid < FEAS) {
        int rl = srow[tid] - b*NN;
        size_t o = (size_t)b*NN*NN + (size_t)rl*NN + scol[tid];
        out[o] = expf(ss[tid] - smx) / ssum;
    }
}

// ------------------------------- host driver ---------------------------------
extern "C" void kernel_launch(void* const* d_in, const int* in_sizes, int n_in,
                              void* d_out, int out_size)
{
    const float* x       = (const float*)d_in[0];
    const int*   ei      = (const int*)  d_in[1];
    const int*   mrows   = (const int*)  d_in[3];
    const int*   mcols   = (const int*)  d_in[4];
    const float* gin0_w1 = (const float*)d_in[5];
    const float* gin0_b1 = (const float*)d_in[6];
    const float* gin0_w2 = (const float*)d_in[7];
    const float* gin0_b2 = (const float*)d_in[8];
    const float* gin_w1  = (const float*)d_in[9];
    const float* gin_b1  = (const float*)d_in[10];
    const float* gin_w2  = (const float*)d_in[11];
    const float* gin_b2  = (const float*)d_in[12];
    const float* bn_g    = (const float*)d_in[13];
    const float* bn_b    = (const float*)d_in[14];
    const float* pol0_w1 = (const float*)d_in[15];
    const float* pol0_b1 = (const float*)d_in[16];
    const float* pol0_w2 = (const float*)d_in[17];
    const float* pol0_b2 = (const float*)d_in[18];
    const float* pol_w1  = (const float*)d_in[19];
    const float* pol_b1  = (const float*)d_in[20];
    const float* pol_w2  = (const float*)d_in[21];
    const float* pol_b2  = (const float*)d_in[22];
    float* out = (float*)d_out;

    const int* src = ei;
    const int* dst = ei + NE;

    float *p_h, *p_t, *p_agg, *p_pool, *p_stats;
    unsigned short* p_wt;
    cudaGetSymbolAddress((void**)&p_h,     g_h);
    cudaGetSymbolAddress((void**)&p_t,     g_t);
    cudaGetSymbolAddress((void**)&p_agg,   g_agg);
    cudaGetSymbolAddress((void**)&p_pool,  g_pool);
    cudaGetSymbolAddress((void**)&p_stats, g_stats);
    cudaGetSymbolAddress((void**)&p_wt,    g_wt);
    auto WT = [&](int m) { return p_wt + (size_t)m*32768; };
    auto ST = [&](int l) { return p_stats + (size_t)l*2*H; };

    cudaFuncSetAttribute(gemm_tc<1,0,0>, cudaFuncAttributeMaxDynamicSharedMemorySize, SM_GEMM);
    cudaFuncSetAttribute(gemm_tc<1,0,1>, cudaFuncAttributeMaxDynamicSharedMemorySize, SM_GEMM);
    cudaFuncSetAttribute(gemm_tc<0,0,0>, cudaFuncAttributeMaxDynamicSharedMemorySize, SM_GEMM);
    cudaFuncSetAttribute(gemm_tc<2,0,0>, cudaFuncAttributeMaxDynamicSharedMemorySize, SM_GEMM);
    cudaFuncSetAttribute(gemm_tc<2,2,0>, cudaFuncAttributeMaxDynamicSharedMemorySize, SM_GEMM);

    cudaMemsetAsync(d_out, 0, (size_t)out_size * sizeof(float), 0);

    wprep<<<dim3(64, NMAT), 256>>>(gin0_w2, gin_w1, gin_w2, pol0_w1, pol0_w2, pol_w1, pol_w2);
    zero_misc<<<NTOT/256, 256>>>();
    deg_count<<<NE/256, 256>>>(dst);
    scan1<<<128, 256>>>();
    scan2<<<1, 128>>>();
    scan3<<<128, 256>>>();
    fill_csr<<<NE/256, 256>>>(src, dst);

    // ---------------- GIN layer 0 (IN=8): raw0 -> g_agg ----------------
    scatter8 <<<NE*2/256, 256>>>(x, src, dst);
    gemm_l0  <<<NTOT*32/256, 256>>>(x, gin0_w1, gin0_b1);
    gemm_tc<1,0,1><<<NTOT/128, 256, SM_GEMM>>>(p_t, gin0_b2, WT(0), p_agg, ST(0));

    // ---------------- GIN layers 1..3 (fused gather+BN) ----------------
    for (int l = 0; l < 3; l++) {
        if (l == 0)
            gather_bn<1><<<NTOT*32/256, 256>>>(p_agg, ST(0), bn_g, bn_b);
        else
            gather_bn<0><<<NTOT*32/256, 256>>>(p_agg, ST(l),
                                               bn_g + (size_t)l*H, bn_b + (size_t)l*H);
        gemm_tc<1,0,0><<<NTOT/128, 256, SM_GEMM>>>(p_t, gin_b1 + l*H, WT(1 + l), p_h, nullptr);
        gemm_tc<1,0,1><<<NTOT/128, 256, SM_GEMM>>>(p_h, gin_b2 + l*H, WT(4 + l), p_agg, ST(l + 1));
    }
    // final BN (layer 3): pool/gpool only
    bn_norm<0,0><<<NTOT*32/256, 256>>>(p_agg, ST(3), bn_g + (size_t)3*H, bn_b + (size_t)3*H);

    // ---------------- policy head on compact 4096 rows ----------------
    gb_kernel<<<BATCH, 128>>>(pol0_w1, pol0_b1);
    gather_pol<<<NPOL*32/256, 256>>>(mrows, mcols);   // g_pool -> g_t (compact)
    gemm_tc<2,2,0><<<NPOL/128, 256, SM_GEMM>>>(p_t, nullptr,    WT(7),  p_h, nullptr);
    gemm_tc<0,0,0><<<NPOL/128, 256, SM_GEMM>>>(p_h, pol0_b2,    WT(8),  p_t, nullptr);
    gemm_tc<2,0,0><<<NPOL/128, 256, SM_GEMM>>>(p_t, pol_b1,     WT(9),  p_h, nullptr);
    gemm_tc<0,0,0><<<NPOL/128, 256, SM_GEMM>>>(p_h, pol_b2,     WT(11), p_t, nullptr);
    gemm_tc<2,0,0><<<NPOL/128, 256, SM_GEMM>>>(p_t, pol_b1 + H, WT(10), p_h, nullptr);
    gemm_tc<0,0,0><<<NPOL/128, 256, SM_GEMM>>>(p_h, pol_b2 + H, WT(12), p_t, nullptr);

    // ---------------- masked score + softmax ----------------
    final_softmax<<<BATCH, 256>>>(p_t, mrows, mcols, out);
}

// round 16
// speedup vs baseline: 1.3034x; 1.1110x over previous
#include <cuda_runtime.h>
#include <cuda_bf16.h>
#include <cstdint>
#include <math.h>

#define BATCH 32
#define NN    1024
#define NTOT  (BATCH*NN)   // 32768
#define NE    262144
#define INF_DIM 8
#define H     128
#define FEAS  64
#define NMAT  13
#define NPOL  (BATCH*128)  // 4096 compact policy rows

// ------------------------- scratch (static device memory) -------------------
__device__ __align__(16) float g_h[NTOT*H];
__device__ __align__(16) float g_t[NTOT*H];
__device__ __align__(16) float g_agg[NTOT*H];
__device__ __align__(16) float g_pool[NTOT*H];
__device__ __align__(16) float g_gp[BATCH*H];
__device__ __align__(16) float g_gb[BATCH*H];
__device__ __align__(16) float g_stats[4*2*H];   // per-BN-layer raw sum/sumsq
__device__ __align__(16) int   g_cnt[NTOT];
__device__ __align__(16) int   g_off[NTOT];
__device__ __align__(16) int   g_cur[NTOT];
__device__ __align__(16) int   g_eidx[NE];
__device__ __align__(16) int   g_bsum[128];
__device__ __align__(16) int   g_boff[128];
// weight images: per mat, W^T hi [n][k] (16384 ushorts) then lo (16384)
__device__ __align__(128) unsigned short g_wt[NMAT*32768];

// ------------------------------ MMA helpers ----------------------------------
__device__ __forceinline__ uint32_t smem_u32(const void* p) {
    uint32_t a;
    asm("{ .reg .u64 t; cvta.to.shared.u64 t, %1; cvt.u32.u64 %0, t; }" : "=r"(a) : "l"(p));
    return a;
}
__device__ __forceinline__ void ldsm_x4(uint32_t& r0, uint32_t& r1, uint32_t& r2,
                                        uint32_t& r3, uint32_t addr) {
    asm volatile("ldmatrix.sync.aligned.m8n8.x4.shared.b16 {%0,%1,%2,%3}, [%4];"
                 : "=r"(r0), "=r"(r1), "=r"(r2), "=r"(r3) : "r"(addr));
}
__device__ __forceinline__ void mma16816(float* c, const uint32_t* a,
                                         uint32_t b0, uint32_t b1) {
    asm volatile("mma.sync.aligned.m16n8k16.row.col.f32.bf16.bf16.f32 "
        "{%0,%1,%2,%3}, {%4,%5,%6,%7}, {%8,%9}, {%0,%1,%2,%3};"
        : "+f"(c[0]), "+f"(c[1]), "+f"(c[2]), "+f"(c[3])
        : "r"(a[0]), "r"(a[1]), "r"(a[2]), "r"(a[3]), "r"(b0), "r"(b1));
}
__device__ __forceinline__ void split2(float2 e, uint32_t& hi, uint32_t& lo) {
    __nv_bfloat162 h = __floats2bfloat162_rn(e.x, e.y);
    float2 f = __bfloat1622float2(h);
    __nv_bfloat162 l = __floats2bfloat162_rn(e.x - f.x, e.y - f.y);
    hi = *(uint32_t*)&h;
    lo = *(uint32_t*)&l;
}

// ------------------------------- small utils --------------------------------
__global__ void zero_misc() {
    int i = blockIdx.x*256 + threadIdx.x;     // 128 blocks -> 32768 threads
    g_cnt[i] = 0;
    ((float2*)g_agg)[i*4]     = make_float2(0.f,0.f);   // zero first NTOT*8 floats
    ((float2*)g_agg)[i*4 + 1] = make_float2(0.f,0.f);
    ((float2*)g_agg)[i*4 + 2] = make_float2(0.f,0.f);
    ((float2*)g_agg)[i*4 + 3] = make_float2(0.f,0.f);
    if (i < BATCH*H) g_gp[i] = 0.f;
    if (i < 4*2*H)   g_stats[i] = 0.f;
}
__global__ void deg_count(const int* __restrict__ dst) {
    int e = blockIdx.x*256 + threadIdx.x;
    if (e < NE) atomicAdd(&g_cnt[dst[e]], 1);
}
// hierarchical scan: block sums -> scan of 128 -> block-local offsets
__global__ void scan1() {                    // 128 blocks x 256
    __shared__ int sh[256];
    int t = threadIdx.x;
    sh[t] = g_cnt[blockIdx.x*256 + t];
    __syncthreads();
    for (int off = 128; off; off >>= 1) {
        if (t < off) sh[t] += sh[t + off];
        __syncthreads();
    }
    if (t == 0) g_bsum[blockIdx.x] = sh[0];
}
__global__ void scan2() {                    // 1 block x 128: exclusive scan
    __shared__ int sh[128];
    int t = threadIdx.x;
    sh[t] = g_bsum[t];
    __syncthreads();
    for (int off = 1; off < 128; off <<= 1) {
        int v = (t >= off) ? sh[t - off] : 0;
        __syncthreads();
        sh[t] += v;
        __syncthreads();
    }
    g_boff[t] = (t > 0) ? sh[t - 1] : 0;
}
__global__ void scan3() {                    // 128 blocks x 256
    __shared__ int sh[256];
    int t = threadIdx.x;
    int i = blockIdx.x*256 + t;
    int c = g_cnt[i];
    sh[t] = c;
    __syncthreads();
    for (int off = 1; off < 256; off <<= 1) {
        int v = (t >= off) ? sh[t - off] : 0;
        __syncthreads();
        sh[t] += v;
        __syncthreads();
    }
    int o = g_boff[blockIdx.x] + sh[t] - c;  // exclusive
    g_off[i] = o;
    g_cur[i] = o;
}
__global__ void fill_csr(const int* __restrict__ src, const int* __restrict__ dst) {
    int e = blockIdx.x*256 + threadIdx.x;
    if (e < NE) {
        int p = atomicAdd(&g_cur[dst[e]], 1);
        g_eidx[p] = src[e];
    }
}

// --------------------------- layer-0 scatter (IN=8) --------------------------
__device__ __forceinline__ void red_add_v4(float* p, float4 v) {
    asm volatile("red.global.add.v4.f32 [%0], {%1,%2,%3,%4};"
                 :: "l"(p), "f"(v.x), "f"(v.y), "f"(v.z), "f"(v.w) : "memory");
}
__global__ void scatter8(const float* __restrict__ x,
                         const int* __restrict__ src, const int* __restrict__ dst) {
    int t = blockIdx.x*256 + threadIdx.x;
    if (t >= NE*2) return;
    int e = t >> 1, c = (t & 1) << 2;
    int s = src[e], d = dst[e];
    float4 v = *(const float4*)(x + (size_t)s*INF_DIM + c);
    red_add_v4(g_agg + (size_t)d*INF_DIM + c, v);
}

// ------- fused gather + inline BN: z = bn(raw_i) + mean_j bn(raw_j) ----------
template<int FIRST>
__global__ __launch_bounds__(256) void gather_bn(
    const float* __restrict__ raw, const float* __restrict__ stats,
    const float* __restrict__ gamma, const float* __restrict__ beta)
{
    __shared__ float sp[H];
    int tid = threadIdx.x;
    if (tid < H) sp[tid] = 0.f;
    __syncthreads();

    int gw   = (blockIdx.x*256 + tid) >> 5;   // dst row (8 rows per block)
    int lane = tid & 31;

    float4 s4 = ((const float4*)stats)[lane];
    float4 w4 = ((const float4*)(stats + H))[lane];
    const float invN = 1.0f/NTOT;
    float4 mu, iv;
    mu.x = s4.x*invN; mu.y = s4.y*invN; mu.z = s4.z*invN; mu.w = s4.w*invN;
    iv.x = rsqrtf(fmaf(-mu.x, mu.x, w4.x*invN) + 1e-5f);
    iv.y = rsqrtf(fmaf(-mu.y, mu.y, w4.y*invN) + 1e-5f);
    iv.z = rsqrtf(fmaf(-mu.z, mu.z, w4.z*invN) + 1e-5f);
    iv.w = rsqrtf(fmaf(-mu.w, mu.w, w4.w*invN) + 1e-5f);
    float4 ga = ((const float4*)gamma)[lane];
    float4 be = ((const float4*)beta)[lane];
    float4 a, b2;
    a.x = iv.x*ga.x; a.y = iv.y*ga.y; a.z = iv.z*ga.z; a.w = iv.w*ga.w;
    b2.x = fmaf(-mu.x, a.x, be.x); b2.y = fmaf(-mu.y, a.y, be.y);
    b2.z = fmaf(-mu.z, a.z, be.z); b2.w = fmaf(-mu.w, a.w, be.w);

    int beg = g_off[gw], cnt = g_cnt[gw];
    const float4* r4 = (const float4*)raw;
    float4 acc = make_float4(0.f,0.f,0.f,0.f);
    for (int e = 0; e < cnt; e++) {
        int s = g_eidx[beg + e];
        float4 v = r4[(size_t)s*32 + lane];
        acc.x += fmaf(v.x, a.x, b2.x); acc.y += fmaf(v.y, a.y, b2.y);
        acc.z += fmaf(v.z, a.z, b2.z); acc.w += fmaf(v.w, a.w, b2.w);
    }
    float inv = 1.f / fmaxf((float)cnt, 1.f);
    float4 hv = r4[(size_t)gw*32 + lane];
    float4 c;
    c.x = fmaf(hv.x, a.x, b2.x); c.y = fmaf(hv.y, a.y, b2.y);
    c.z = fmaf(hv.z, a.z, b2.z); c.w = fmaf(hv.w, a.w, b2.w);
    float4 z;
    z.x = fmaf(acc.x, inv, c.x); z.y = fmaf(acc.y, inv, c.y);
    z.z = fmaf(acc.z, inv, c.z); z.w = fmaf(acc.w, inv, c.w);
    ((float4*)g_t)[(size_t)gw*32 + lane] = z;

    float4 p;
    if (FIRST) {
        p = c;
    } else {
        p = ((float4*)g_pool)[(size_t)gw*32 + lane];
        p.x += c.x; p.y += c.y; p.z += c.z; p.w += c.w;
    }
    ((float4*)g_pool)[(size_t)gw*32 + lane] = p;

    atomicAdd(&sp[lane*4 + 0], c.x);
    atomicAdd(&sp[lane*4 + 1], c.y);
    atomicAdd(&sp[lane*4 + 2], c.z);
    atomicAdd(&sp[lane*4 + 3], c.w);
    __syncthreads();
    if (tid < H) {
        int b = blockIdx.x >> 7;   // 128 blocks per batch (8 rows/block)
        atomicAdd(&g_gp[b*H + tid], sp[tid] * (1.0f/NN));
    }
}

// ------------------- weight prep: split bf16, W^T [n][k] ---------------------
__global__ void wprep(const float* __restrict__ gin0_w2, const float* __restrict__ gin_w1,
                      const float* __restrict__ gin_w2, const float* __restrict__ pol0_w1,
                      const float* __restrict__ pol0_w2, const float* __restrict__ pol_w1,
                      const float* __restrict__ pol_w2) {
    int mat = blockIdx.y;
    const float* W;
    if      (mat == 0)  W = gin0_w2;
    else if (mat < 4)   W = gin_w1 + (size_t)(mat-1)*H*H;
    else if (mat < 7)   W = gin_w2 + (size_t)(mat-4)*H*H;
    else if (mat == 7)  W = pol0_w1;                    // first 128 rows
    else if (mat == 8)  W = pol0_w2;
    else if (mat < 11)  W = pol_w1 + (size_t)(mat-9)*H*H;
    else                W = pol_w2 + (size_t)(mat-11)*H*H;
    int idx = blockIdx.x*256 + threadIdx.x;             // 0..16383
    int n = idx >> 7, k = idx & 127;
    float el = W[(size_t)k*H + n];                      // B[n][k] = W[k][n]
    __nv_bfloat16 hb = __float2bfloat16(el);
    __nv_bfloat16 lb = __float2bfloat16(el - __bfloat162float(hb));
    unsigned short* base = g_wt + (size_t)mat*32768;
    base[idx]         = *(unsigned short*)&hb;
    base[16384 + idx] = *(unsigned short*)&lb;
}

// ------------------- HMMA GEMM: C[N,128] = epi(A@W + bias) -------------------
// split-bf16: C = Ahi*Bhi + Ahi*Blo + Alo*Bhi  (fp32 accum)
// 256 threads, 8 warps = 4M x 2N over a 128x128 tile (R9 core).
// EPI: 0 none, 1 relu.  STATS: column sum/sumsq into stats buffer (for BN).
#define BSTRIDE 136
#define SM_GEMM (2*128*BSTRIDE*2 + 512 + 1024)

template<int EPI, int STATS>
__global__ __launch_bounds__(256) void gemm_tc(
    const float* __restrict__ A, const float* __restrict__ bias,
    const unsigned short* __restrict__ Bt, float* __restrict__ C,
    float* __restrict__ stats)
{
    extern __shared__ __align__(16) char smem[];
    __nv_bfloat16* sBhi = (__nv_bfloat16*)smem;
    __nv_bfloat16* sBlo = sBhi + 128*BSTRIDE;
    float* sBias = (float*)(sBlo + 128*BSTRIDE);
    float* sSum  = sBias + 128;
    float* sSq   = sSum + 128;

    int tid = threadIdx.x;
    int wid = tid >> 5, lane = tid & 31;
    int wm = wid & 3, wn = wid >> 2;       // 4 M-warps x 2 N-warps
    int m0 = blockIdx.x * 128;

    if (tid < 128) {
        sBias[tid] = bias[tid];
        if (STATS) { sSum[tid] = 0.f; sSq[tid] = 0.f; }
    }
    {
        const uint4* Bg = (const uint4*)Bt;   // 4096 uint4 (hi 2048, lo 2048)
#pragma unroll
        for (int i = tid; i < 4096; i += 256) {
            int half = i >> 11;
            int j = i & 2047;
            int row = j >> 4, c = j & 15;
            __nv_bfloat16* d = (half ? sBlo : sBhi) + row*BSTRIDE + c*8;
            *(uint4*)d = Bg[i];
        }
    }
    __syncthreads();

    float acc[2][8][4];
#pragma unroll
    for (int mt = 0; mt < 2; mt++)
#pragma unroll
        for (int nt = 0; nt < 8; nt++)
#pragma unroll
            for (int q = 0; q < 4; q++) acc[mt][nt][q] = 0.f;

    int rbase = m0 + wm*32 + (lane >> 2);
    int cbase = (lane & 3)*2;
    int g  = lane >> 3, lr = lane & 7;
    const __nv_bfloat16* lbase = (g & 2) ? sBlo : sBhi;
    int kofs = (g & 1)*8;

#pragma unroll
    for (int k = 0; k < 8; k++) {
        int k0 = k*16;
        uint32_t ahi[2][4], alo[2][4];
#pragma unroll
        for (int mt = 0; mt < 2; mt++) {
            const float* Ar0 = A + (size_t)(rbase + mt*16)*H + k0 + cbase;
            const float* Ar1 = Ar0 + 8*H;
            split2(*(const float2*)Ar0,       ahi[mt][0], alo[mt][0]);
            split2(*(const float2*)Ar1,       ahi[mt][1], alo[mt][1]);
            split2(*(const float2*)(Ar0 + 8), ahi[mt][2], alo[mt][2]);
            split2(*(const float2*)(Ar1 + 8), ahi[mt][3], alo[mt][3]);
        }
#pragma unroll
        for (int nt = 0; nt < 8; nt++) {
            int n0 = wn*64 + nt*8;
            uint32_t addr = smem_u32(lbase + (size_t)(n0 + lr)*BSTRIDE + k0 + kofs);
            uint32_t bh0, bh1, bl0, bl1;
            ldsm_x4(bh0, bh1, bl0, bl1, addr);
#pragma unroll
            for (int mt = 0; mt < 2; mt++) {
                mma16816(acc[mt][nt], ahi[mt], bh0, bh1);
                mma16816(acc[mt][nt], ahi[mt], bl0, bl1);
                mma16816(acc[mt][nt], alo[mt], bh0, bh1);
            }
        }
    }

    float s0[8], s1[8], q0[8], q1[8];
    if (STATS) {
#pragma unroll
        for (int nt = 0; nt < 8; nt++) { s0[nt]=0.f; s1[nt]=0.f; q0[nt]=0.f; q1[nt]=0.f; }
    }
#pragma unroll
    for (int mt = 0; mt < 2; mt++) {
        int r0 = m0 + wm*32 + mt*16 + (lane >> 2);
#pragma unroll
        for (int nt = 0; nt < 8; nt++) {
            int col = wn*64 + nt*8 + (lane & 3)*2;
            float bx = sBias[col], by = sBias[col + 1];
            float v0 = acc[mt][nt][0] + bx, v1 = acc[mt][nt][1] + by;
            float v2 = acc[mt][nt][2] + bx, v3 = acc[mt][nt][3] + by;
            if (EPI == 1) {
                v0 = fmaxf(v0, 0.f); v1 = fmaxf(v1, 0.f);
                v2 = fmaxf(v2, 0.f); v3 = fmaxf(v3, 0.f);
            }
            if (STATS) {
                s0[nt] += v0 + v2;  s1[nt] += v1 + v3;
                q0[nt] = fmaf(v0, v0, fmaf(v2, v2, q0[nt]));
                q1[nt] = fmaf(v1, v1, fmaf(v3, v3, q1[nt]));
            }
            *(float2*)(C + (size_t)r0*H + col)       = make_float2(v0, v1);
            *(float2*)(C + (size_t)(r0 + 8)*H + col) = make_float2(v2, v3);
        }
    }
    if (STATS) {
#pragma unroll
        for (int nt = 0; nt < 8; nt++) {
#pragma unroll
            for (int off = 4; off < 32; off <<= 1) {
                s0[nt] += __shfl_xor_sync(0xffffffffu, s0[nt], off);
                s1[nt] += __shfl_xor_sync(0xffffffffu, s1[nt], off);
                q0[nt] += __shfl_xor_sync(0xffffffffu, q0[nt], off);
                q1[nt] += __shfl_xor_sync(0xffffffffu, q1[nt], off);
            }
            if (lane < 4) {
                int col = wn*64 + nt*8 + lane*2;
                atomicAdd(&sSum[col],     s0[nt]);
                atomicAdd(&sSum[col + 1], s1[nt]);
                atomicAdd(&sSq[col],      q0[nt]);
                atomicAdd(&sSq[col + 1],  q1[nt]);
            }
        }
        __syncthreads();
        if (tid < 128) {
            atomicAdd(&stats[tid],     sSum[tid]);
            atomicAdd(&stats[H + tid], sSq[tid]);
        }
    }
}

// ---------------- fused 6-layer policy MLP on compact rows -------------------
// grid=128 CTAs, each owns 32 compact rows; z kept in smem across layers.
// mats order {7,8,9,11,10,12}; epi tanh on even layers; biases per layer.
#define PZSTRIDE 132
#define SM_POL (2*128*BSTRIDE*2 + 32*PZSTRIDE*4 + 512)

__global__ __launch_bounds__(256) void policy_fused(
    const unsigned short* __restrict__ wt,
    const float* __restrict__ pol0_b2, const float* __restrict__ pol_b1,
    const float* __restrict__ pol_b2)
{
    extern __shared__ __align__(16) char smem[];
    __nv_bfloat16* sBhi = (__nv_bfloat16*)smem;
    __nv_bfloat16* sBlo = sBhi + 128*BSTRIDE;
    float* sZ    = (float*)(sBlo + 128*BSTRIDE);
    float* sBias = sZ + 32*PZSTRIDE;

    int tid = threadIdx.x;
    int wid = tid >> 5, lane = tid & 31;
    int wm = wid & 1, wn = wid >> 1;       // 2 M-warps(16) x 4 N-warps(32)
    int r0 = blockIdx.x * 32;
    int b  = blockIdx.x >> 2;

    // load compact z rows into smem
    for (int i = tid; i < 32*32; i += 256) {
        int row = i >> 5, c4 = i & 31;
        float4 v = ((const float4*)g_t)[(size_t)(r0 + row)*32 + c4];
        *(float4*)&sZ[row*PZSTRIDE + c4*4] = v;
    }

    const int mats[6] = {7, 8, 9, 11, 10, 12};
    int g  = lane >> 3, lr = lane & 7;
    const __nv_bfloat16* lbase = (g & 2) ? sBlo : sBhi;
    int kofs = (g & 1)*8;
    int arow = wm*16 + (lane >> 2);
    int acol = (lane & 3)*2;

#pragma unroll 1
    for (int l = 0; l < 6; l++) {
        __syncthreads();   // prior z writes visible; prior W reads done
        const uint4* Bg = (const uint4*)(wt + (size_t)mats[l]*32768);
#pragma unroll
        for (int i = tid; i < 4096; i += 256) {
            int half = i >> 11;
            int j = i & 2047;
            int row = j >> 4, c = j & 15;
            __nv_bfloat16* d = (half ? sBlo : sBhi) + row*BSTRIDE + c*8;
            *(uint4*)d = Bg[i];
        }
        if (tid < 128) {
            const float* bp;
            if      (l == 0) bp = g_gb + (size_t)b*H;
            else if (l == 1) bp = pol0_b2;
            else if (l == 2) bp = pol_b1;
            else if (l == 3) bp = pol_b2;
            else if (l == 4) bp = pol_b1 + H;
            else             bp = pol_b2 + H;
            sBias[tid] = bp[tid];
        }
        __syncthreads();

        float acc[4][4];
#pragma unroll
        for (int nt = 0; nt < 4; nt++)
#pragma unroll
            for (int q = 0; q < 4; q++) acc[nt][q] = 0.f;

#pragma unroll
        for (int k = 0; k < 8; k++) {
            int k0 = k*16;
            uint32_t ahi[4], alo[4];
            split2(*(const float2*)&sZ[arow*PZSTRIDE + k0 + acol],           ahi[0], alo[0]);
            split2(*(const float2*)&sZ[(arow + 8)*PZSTRIDE + k0 + acol],     ahi[1], alo[1]);
            split2(*(const float2*)&sZ[arow*PZSTRIDE + k0 + acol + 8],       ahi[2], alo[2]);
            split2(*(const float2*)&sZ[(arow + 8)*PZSTRIDE + k0 + acol + 8], ahi[3], alo[3]);
#pragma unroll
            for (int nt = 0; nt < 4; nt++) {
                int n0 = wn*32 + nt*8;
                uint32_t addr = smem_u32(lbase + (size_t)(n0 + lr)*BSTRIDE + k0 + kofs);
                uint32_t bh0, bh1, bl0, bl1;
                ldsm_x4(bh0, bh1, bl0, bl1, addr);
                mma16816(acc[nt], ahi, bh0, bh1);
                mma16816(acc[nt], ahi, bl0, bl1);
                mma16816(acc[nt], alo, bh0, bh1);
            }
        }
        __syncthreads();   // all reads of sZ done before overwrite

        int ro = wm*16 + (lane >> 2);
#pragma unroll
        for (int nt = 0; nt < 4; nt++) {
            int col = wn*32 + nt*8 + (lane & 3)*2;
            float bx = sBias[col], by = sBias[col + 1];
            float v0 = acc[nt][0] + bx, v1 = acc[nt][1] + by;
            float v2 = acc[nt][2] + bx, v3 = acc[nt][3] + by;
            if ((l & 1) == 0) {
                v0 = tanhf(v0); v1 = tanhf(v1);
                v2 = tanhf(v2); v3 = tanhf(v3);
            }
            *(float2*)&sZ[ro*PZSTRIDE + col]       = make_float2(v0, v1);
            *(float2*)&sZ[(ro + 8)*PZSTRIDE + col] = make_float2(v2, v3);
        }
    }
    __syncthreads();

    // write final z back to compact g_t
    for (int i = tid; i < 32*32; i += 256) {
        int row = i >> 5, c4 = i & 31;
        ((float4*)g_t)[(size_t)(r0 + row)*32 + c4] = *(float4*)&sZ[row*PZSTRIDE + c4*4];
    }
}

// layer-0 first linear: K = 8, z-fold, relu.  out -> g_t
__global__ __launch_bounds__(256) void gemm_l0(
    const float* __restrict__ x, const float* __restrict__ w1,
    const float* __restrict__ b1)
{
    __shared__ float sW[INF_DIM*H];
    __shared__ float sB[H];
    int tid = threadIdx.x;
    for (int i = tid; i < INF_DIM*H; i += 256) sW[i] = w1[i];
    if (tid < H) sB[tid] = b1[tid];
    __syncthreads();

    int t   = blockIdx.x*256 + tid;
    int row = t >> 5, cg = t & 31;
    float id = 1.f / fmaxf((float)g_cnt[row], 1.f);
    const float4* x4 = (const float4*)x;
    const float4* g4 = (const float4*)g_agg;
    float4 a0 = x4[(size_t)row*2],   a1 = x4[(size_t)row*2 + 1];
    float4 q0 = g4[(size_t)row*2],   q1 = g4[(size_t)row*2 + 1];
    float z[8] = { fmaf(q0.x,id,a0.x), fmaf(q0.y,id,a0.y), fmaf(q0.z,id,a0.z), fmaf(q0.w,id,a0.w),
                   fmaf(q1.x,id,a1.x), fmaf(q1.y,id,a1.y), fmaf(q1.z,id,a1.z), fmaf(q1.w,id,a1.w) };
    const float4* sW4 = (const float4*)sW;
    float4 acc = ((const float4*)sB)[cg];
#pragma unroll
    for (int k = 0; k < 8; k++) {
        float4 w = sW4[k*32 + cg];
        acc.x = fmaf(z[k], w.x, acc.x); acc.y = fmaf(z[k], w.y, acc.y);
        acc.z = fmaf(z[k], w.z, acc.z); acc.w = fmaf(z[k], w.w, acc.w);
    }
    acc.x = fmaxf(acc.x, 0.f); acc.y = fmaxf(acc.y, 0.f);
    acc.z = fmaxf(acc.z, 0.f); acc.w = fmaxf(acc.w, 0.f);
    ((float4*)g_t)[(size_t)row*32 + cg] = acc;
}

// ------------------------------ batch norm (final layer) ----------------------
template<int FIRST, int STORE>
__global__ __launch_bounds__(256) void bn_norm(
    const float* __restrict__ r, const float* __restrict__ stats,
    const float* __restrict__ gamma, const float* __restrict__ beta)
{
    __shared__ float sp[H];
    int tid = threadIdx.x;
    if (tid < H) sp[tid] = 0.f;
    __syncthreads();

    int idx = blockIdx.x*256 + tid;   // NTOT*32 float4s
    int cg  = idx & 31;
    float4 v  = ((const float4*)r)[idx];
    float4 s4 = ((const float4*)stats)[cg];
    float4 w4 = ((const float4*)(stats + H))[cg];
    const float invN = 1.0f/NTOT;
    float4 mu, iv;
    mu.x = s4.x*invN; mu.y = s4.y*invN; mu.z = s4.z*invN; mu.w = s4.w*invN;
    iv.x = rsqrtf(fmaf(-mu.x, mu.x, w4.x*invN) + 1e-5f);
    iv.y = rsqrtf(fmaf(-mu.y, mu.y, w4.y*invN) + 1e-5f);
    iv.z = rsqrtf(fmaf(-mu.z, mu.z, w4.z*invN) + 1e-5f);
    iv.w = rsqrtf(fmaf(-mu.w, mu.w, w4.w*invN) + 1e-5f);
    float4 ga = ((const float4*)gamma)[cg];
    float4 be = ((const float4*)beta)[cg];
    float4 c;
    c.x = fmaf((v.x - mu.x)*iv.x, ga.x, be.x);
    c.y = fmaf((v.y - mu.y)*iv.y, ga.y, be.y);
    c.z = fmaf((v.z - mu.z)*iv.z, ga.z, be.z);
    c.w = fmaf((v.w - mu.w)*iv.w, ga.w, be.w);
    if (STORE) ((float4*)g_h)[idx] = c;
    if (FIRST) {
        ((float4*)g_pool)[idx] = c;
    } else {
        float4 p = ((float4*)g_pool)[idx];
        p.x += c.x; p.y += c.y; p.z += c.z; p.w += c.w;
        ((float4*)g_pool)[idx] = p;
    }
    atomicAdd(&sp[cg*4 + 0], c.x);
    atomicAdd(&sp[cg*4 + 1], c.y);
    atomicAdd(&sp[cg*4 + 2], c.z);
    atomicAdd(&sp[cg*4 + 3], c.w);
    __syncthreads();
    if (tid < H) {
        int b = blockIdx.x >> 7;   // 128 blocks per batch (8 rows/block)
        atomicAdd(&g_gp[b*H + tid], sp[tid] * (1.0f/NN));
    }
}

// per-batch policy bias: gb[b] = gpool[b] @ pol0_w1[128:256,:] + pol0_b1
__global__ void gb_kernel(const float* __restrict__ w1, const float* __restrict__ b1) {
    int b = blockIdx.x, n = threadIdx.x;
    __shared__ float sg[H];
    sg[n] = g_gp[b*H + n];
    __syncthreads();
    float acc = b1[n];
#pragma unroll 8
    for (int k = 0; k < H; k++) acc = fmaf(sg[k], w1[(size_t)(H + k)*H + n], acc);
    g_gb[b*H + n] = acc;
}

// ------- compact policy rows: slot b*128+j <- pool[mask row or col row] ------
__global__ __launch_bounds__(256) void gather_pol(
    const int* __restrict__ mrows, const int* __restrict__ mcols)
{
    int s    = (blockIdx.x*256 + threadIdx.x) >> 5;   // 0..NPOL-1
    int lane = threadIdx.x & 31;
    int b = s >> 7, j = s & 127;
    int src = (j < FEAS) ? mrows[b*FEAS + j] : (b*NN + mcols[b*FEAS + j - FEAS]);
    float4 v = ((const float4*)g_pool)[(size_t)src*32 + lane];
    ((float4*)g_t)[(size_t)s*32 + lane] = v;
}

// ---------------------- final: masked score + softmax ------------------------
__global__ void final_softmax(const float* __restrict__ zc,
                              const int* __restrict__ mrows,
                              const int* __restrict__ mcols,
                              float* __restrict__ out)
{
    __shared__ int   srow[FEAS], scol[FEAS], sdup[FEAS];
    __shared__ float ss[FEAS];
    __shared__ float smx, ssum;
    int b = blockIdx.x, tid = threadIdx.x;
    if (tid < FEAS) {
        srow[tid] = mrows[b*FEAS + tid];
        scol[tid] = mcols[b*FEAS + tid];
    }
    __syncthreads();
    int lane = tid & 31, w = tid >> 5;
    for (int j = w; j < FEAS; j += 8) {
        const float* zr = zc + (size_t)(b*128 + j)*H;
        const float* zl = zc + (size_t)(b*128 + FEAS + j)*H;
        float s = 0.f;
        for (int k = lane; k < H; k += 32) s = fmaf(zr[k], zl[k], s);
#pragma unroll
        for (int o = 16; o; o >>= 1) s += __shfl_xor_sync(0xffffffffu, s, o);
        if (lane == 0) ss[j] = s;
    }
    __syncthreads();
    if (tid < FEAS) {
        int dup = 0;
        for (int k = 0; k < tid; k++)
            if (srow[k] == srow[tid] && scol[k] == scol[tid]) dup = 1;
        sdup[tid] = dup;
    }
    __syncthreads();
    if (tid == 0) {
        float mx = -1e30f;
        for (int j = 0; j < FEAS; j++) if (!sdup[j] && ss[j] > mx) mx = ss[j];
        float sum = 0.f;
        for (int j = 0; j < FEAS; j++) if (!sdup[j]) sum += expf(ss[j] - mx);
        smx = mx; ssum = sum;
    }
    __syncthreads();
    if (tid < FEAS) {
        int rl = srow[tid] - b*NN;
        size_t o = (size_t)b*NN*NN + (size_t)rl*NN + scol[tid];
        out[o] = expf(ss[tid] - smx) / ssum;
    }
}

// ------------------------------- host driver ---------------------------------
extern "C" void kernel_launch(void* const* d_in, const int* in_sizes, int n_in,
                              void* d_out, int out_size)
{
    const float* x       = (const float*)d_in[0];
    const int*   ei      = (const int*)  d_in[1];
    const int*   mrows   = (const int*)  d_in[3];
    const int*   mcols   = (const int*)  d_in[4];
    const float* gin0_w1 = (const float*)d_in[5];
    const float* gin0_b1 = (const float*)d_in[6];
    const float* gin0_w2 = (const float*)d_in[7];
    const float* gin0_b2 = (const float*)d_in[8];
    const float* gin_w1  = (const float*)d_in[9];
    const float* gin_b1  = (const float*)d_in[10];
    const float* gin_w2  = (const float*)d_in[11];
    const float* gin_b2  = (const float*)d_in[12];
    const float* bn_g    = (const float*)d_in[13];
    const float* bn_b    = (const float*)d_in[14];
    const float* pol0_w1 = (const float*)d_in[15];
    const float* pol0_b1 = (const float*)d_in[16];
    const float* pol0_w2 = (const float*)d_in[17];
    const float* pol0_b2 = (const float*)d_in[18];
    const float* pol_w1  = (const float*)d_in[19];
    const float* pol_b1  = (const float*)d_in[20];
    const float* pol_w2  = (const float*)d_in[21];
    const float* pol_b2  = (const float*)d_in[22];
    float* out = (float*)d_out;

    const int* src = ei;
    const int* dst = ei + NE;

    float *p_h, *p_t, *p_agg, *p_pool, *p_stats;
    unsigned short* p_wt;
    cudaGetSymbolAddress((void**)&p_h,     g_h);
    cudaGetSymbolAddress((void**)&p_t,     g_t);
    cudaGetSymbolAddress((void**)&p_agg,   g_agg);
    cudaGetSymbolAddress((void**)&p_pool,  g_pool);
    cudaGetSymbolAddress((void**)&p_stats, g_stats);
    cudaGetSymbolAddress((void**)&p_wt,    g_wt);
    auto WT = [&](int m) { return p_wt + (size_t)m*32768; };
    auto ST = [&](int l) { return p_stats + (size_t)l*2*H; };

    cudaFuncSetAttribute(gemm_tc<1,0>, cudaFuncAttributeMaxDynamicSharedMemorySize, SM_GEMM);
    cudaFuncSetAttribute(gemm_tc<1,1>, cudaFuncAttributeMaxDynamicSharedMemorySize, SM_GEMM);
    cudaFuncSetAttribute(policy_fused, cudaFuncAttributeMaxDynamicSharedMemorySize, SM_POL);

    cudaMemsetAsync(d_out, 0, (size_t)out_size * sizeof(float), 0);

    wprep<<<dim3(64, NMAT), 256>>>(gin0_w2, gin_w1, gin_w2, pol0_w1, pol0_w2, pol_w1, pol_w2);
    zero_misc<<<NTOT/256, 256>>>();
    deg_count<<<NE/256, 256>>>(dst);
    scan1<<<128, 256>>>();
    scan2<<<1, 128>>>();
    scan3<<<128, 256>>>();
    fill_csr<<<NE/256, 256>>>(src, dst);

    // ---------------- GIN layer 0 (IN=8): raw0 -> g_agg ----------------
    scatter8 <<<NE*2/256, 256>>>(x, src, dst);
    gemm_l0  <<<NTOT*32/256, 256>>>(x, gin0_w1, gin0_b1);
    gemm_tc<1,1><<<NTOT/128, 256, SM_GEMM>>>(p_t, gin0_b2, WT(0), p_agg, ST(0));

    // ---------------- GIN layers 1..3 (fused gather+BN) ----------------
    for (int l = 0; l < 3; l++) {
        if (l == 0)
            gather_bn<1><<<NTOT*32/256, 256>>>(p_agg, ST(0), bn_g, bn_b);
        else
            gather_bn<0><<<NTOT*32/256, 256>>>(p_agg, ST(l),
                                               bn_g + (size_t)l*H, bn_b + (size_t)l*H);
        gemm_tc<1,0><<<NTOT/128, 256, SM_GEMM>>>(p_t, gin_b1 + l*H, WT(1 + l), p_h, nullptr);
        gemm_tc<1,1><<<NTOT/128, 256, SM_GEMM>>>(p_h, gin_b2 + l*H, WT(4 + l), p_agg, ST(l + 1));
    }
    // final BN (layer 3): pool/gpool only
    bn_norm<0,0><<<NTOT*32/256, 256>>>(p_agg, ST(3), bn_g + (size_t)3*H, bn_b + (size_t)3*H);

    // ---------------- policy head: compact rows + fused 6-layer MLP ----------
    gb_kernel<<<BATCH, 128>>>(pol0_w1, pol0_b1);
    gather_pol<<<NPOL*32/256, 256>>>(mrows, mcols);   // g_pool -> g_t (compact)
    policy_fused<<<128, 256, SM_POL>>>(p_wt, pol0_b2, pol_b1, pol_b2);

    // ---------------- masked score + softmax ----------------
    final_softmax<<<BATCH, 256>>>(p_t, mrows, mcols, out);
}

// round 17
// speedup vs baseline: 1.3449x; 1.0318x over previous
#include <cuda_runtime.h>
#include <cuda_bf16.h>
#include <cstdint>
#include <math.h>

#define BATCH 32
#define NN    1024
#define NTOT  (BATCH*NN)   // 32768
#define NE    262144
#define INF_DIM 8
#define H     128
#define FEAS  64
#define NMAT  13
#define NPOL  (BATCH*128)  // 4096 compact policy rows

// ------------------------- scratch (static device memory) -------------------
__device__ __align__(16) float g_h[NTOT*H];
__device__ __align__(16) float g_t[NTOT*H];
__device__ __align__(16) float g_agg[NTOT*H];
__device__ __align__(16) float g_pool[NTOT*H];
__device__ __align__(16) float g_gp[BATCH*H];
__device__ __align__(16) float g_gb[BATCH*H];
__device__ __align__(16) float g_stats[4*2*H];   // per-BN-layer raw sum/sumsq
__device__ __align__(16) int   g_cnt[NTOT];
__device__ __align__(16) int   g_off[NTOT];
__device__ __align__(16) int   g_cur[NTOT];
__device__ __align__(16) int   g_eidx[NE];
__device__ __align__(16) int   g_bsum[128];
__device__ __align__(16) int   g_boff[128];
// weight images: per mat, W^T hi [n][k] (16384 ushorts) then lo (16384)
__device__ __align__(128) unsigned short g_wt[NMAT*32768];

// ------------------------------ MMA helpers ----------------------------------
__device__ __forceinline__ uint32_t smem_u32(const void* p) {
    uint32_t a;
    asm("{ .reg .u64 t; cvta.to.shared.u64 t, %1; cvt.u32.u64 %0, t; }" : "=r"(a) : "l"(p));
    return a;
}
__device__ __forceinline__ void ldsm_x4(uint32_t& r0, uint32_t& r1, uint32_t& r2,
                                        uint32_t& r3, uint32_t addr) {
    asm volatile("ldmatrix.sync.aligned.m8n8.x4.shared.b16 {%0,%1,%2,%3}, [%4];"
                 : "=r"(r0), "=r"(r1), "=r"(r2), "=r"(r3) : "r"(addr));
}
__device__ __forceinline__ void mma16816(float* c, const uint32_t* a,
                                         uint32_t b0, uint32_t b1) {
    asm volatile("mma.sync.aligned.m16n8k16.row.col.f32.bf16.bf16.f32 "
        "{%0,%1,%2,%3}, {%4,%5,%6,%7}, {%8,%9}, {%0,%1,%2,%3};"
        : "+f"(c[0]), "+f"(c[1]), "+f"(c[2]), "+f"(c[3])
        : "r"(a[0]), "r"(a[1]), "r"(a[2]), "r"(a[3]), "r"(b0), "r"(b1));
}
__device__ __forceinline__ void split2(float2 e, uint32_t& hi, uint32_t& lo) {
    __nv_bfloat162 h = __floats2bfloat162_rn(e.x, e.y);
    float2 f = __bfloat1622float2(h);
    __nv_bfloat162 l = __floats2bfloat162_rn(e.x - f.x, e.y - f.y);
    hi = *(uint32_t*)&h;
    lo = *(uint32_t*)&l;
}

// ------------------------------- small utils --------------------------------
__global__ void zero_misc() {
    int i = blockIdx.x*256 + threadIdx.x;     // 128 blocks -> 32768 threads
    g_cnt[i] = 0;
    ((float2*)g_agg)[i*4]     = make_float2(0.f,0.f);   // zero first NTOT*8 floats
    ((float2*)g_agg)[i*4 + 1] = make_float2(0.f,0.f);
    ((float2*)g_agg)[i*4 + 2] = make_float2(0.f,0.f);
    ((float2*)g_agg)[i*4 + 3] = make_float2(0.f,0.f);
    if (i < BATCH*H) g_gp[i] = 0.f;
    if (i < 4*2*H)   g_stats[i] = 0.f;
}
__global__ void deg_count(const int* __restrict__ dst) {
    int e = blockIdx.x*256 + threadIdx.x;
    if (e < NE) atomicAdd(&g_cnt[dst[e]], 1);
}
// hierarchical scan: block sums -> scan of 128 -> block-local offsets
__global__ void scan1() {                    // 128 blocks x 256
    __shared__ int sh[256];
    int t = threadIdx.x;
    sh[t] = g_cnt[blockIdx.x*256 + t];
    __syncthreads();
    for (int off = 128; off; off >>= 1) {
        if (t < off) sh[t] += sh[t + off];
        __syncthreads();
    }
    if (t == 0) g_bsum[blockIdx.x] = sh[0];
}
__global__ void scan2() {                    // 1 block x 128: exclusive scan
    __shared__ int sh[128];
    int t = threadIdx.x;
    sh[t] = g_bsum[t];
    __syncthreads();
    for (int off = 1; off < 128; off <<= 1) {
        int v = (t >= off) ? sh[t - off] : 0;
        __syncthreads();
        sh[t] += v;
        __syncthreads();
    }
    g_boff[t] = (t > 0) ? sh[t - 1] : 0;
}
__global__ void scan3() {                    // 128 blocks x 256
    __shared__ int sh[256];
    int t = threadIdx.x;
    int i = blockIdx.x*256 + t;
    int c = g_cnt[i];
    sh[t] = c;
    __syncthreads();
    for (int off = 1; off < 256; off <<= 1) {
        int v = (t >= off) ? sh[t - off] : 0;
        __syncthreads();
        sh[t] += v;
        __syncthreads();
    }
    int o = g_boff[blockIdx.x] + sh[t] - c;  // exclusive
    g_off[i] = o;
    g_cur[i] = o;
}
__global__ void fill_csr(const int* __restrict__ src, const int* __restrict__ dst) {
    int e = blockIdx.x*256 + threadIdx.x;
    if (e < NE) {
        int p = atomicAdd(&g_cur[dst[e]], 1);
        g_eidx[p] = src[e];
    }
}

// --------------------------- layer-0 scatter (IN=8) --------------------------
__device__ __forceinline__ void red_add_v4(float* p, float4 v) {
    asm volatile("red.global.add.v4.f32 [%0], {%1,%2,%3,%4};"
                 :: "l"(p), "f"(v.x), "f"(v.y), "f"(v.z), "f"(v.w) : "memory");
}
__global__ void scatter8(const float* __restrict__ x,
                         const int* __restrict__ src, const int* __restrict__ dst) {
    int t = blockIdx.x*256 + threadIdx.x;
    if (t >= NE*2) return;
    int e = t >> 1, c = (t & 1) << 2;
    int s = src[e], d = dst[e];
    float4 v = *(const float4*)(x + (size_t)s*INF_DIM + c);
    red_add_v4(g_agg + (size_t)d*INF_DIM + c, v);
}

// ------- fused gather + inline BN: z = bn(raw_i) + mean_j bn(raw_j) ----------
template<int FIRST>
__global__ __launch_bounds__(256) void gather_bn(
    const float* __restrict__ raw, const float* __restrict__ stats,
    const float* __restrict__ gamma, const float* __restrict__ beta)
{
    __shared__ float sp[H];
    int tid = threadIdx.x;
    if (tid < H) sp[tid] = 0.f;
    __syncthreads();

    int gw   = (blockIdx.x*256 + tid) >> 5;   // dst row (8 rows per block)
    int lane = tid & 31;

    float4 s4 = ((const float4*)stats)[lane];
    float4 w4 = ((const float4*)(stats + H))[lane];
    const float invN = 1.0f/NTOT;
    float4 mu, iv;
    mu.x = s4.x*invN; mu.y = s4.y*invN; mu.z = s4.z*invN; mu.w = s4.w*invN;
    iv.x = rsqrtf(fmaf(-mu.x, mu.x, w4.x*invN) + 1e-5f);
    iv.y = rsqrtf(fmaf(-mu.y, mu.y, w4.y*invN) + 1e-5f);
    iv.z = rsqrtf(fmaf(-mu.z, mu.z, w4.z*invN) + 1e-5f);
    iv.w = rsqrtf(fmaf(-mu.w, mu.w, w4.w*invN) + 1e-5f);
    float4 ga = ((const float4*)gamma)[lane];
    float4 be = ((const float4*)beta)[lane];
    float4 a, b2;
    a.x = iv.x*ga.x; a.y = iv.y*ga.y; a.z = iv.z*ga.z; a.w = iv.w*ga.w;
    b2.x = fmaf(-mu.x, a.x, be.x); b2.y = fmaf(-mu.y, a.y, be.y);
    b2.z = fmaf(-mu.z, a.z, be.z); b2.w = fmaf(-mu.w, a.w, be.w);

    int beg = g_off[gw], cnt = g_cnt[gw];
    const float4* r4 = (const float4*)raw;
    float4 acc = make_float4(0.f,0.f,0.f,0.f);
    for (int e = 0; e < cnt; e++) {
        int s = g_eidx[beg + e];
        float4 v = r4[(size_t)s*32 + lane];
        acc.x += fmaf(v.x, a.x, b2.x); acc.y += fmaf(v.y, a.y, b2.y);
        acc.z += fmaf(v.z, a.z, b2.z); acc.w += fmaf(v.w, a.w, b2.w);
    }
    float inv = 1.f / fmaxf((float)cnt, 1.f);
    float4 hv = r4[(size_t)gw*32 + lane];
    float4 c;
    c.x = fmaf(hv.x, a.x, b2.x); c.y = fmaf(hv.y, a.y, b2.y);
    c.z = fmaf(hv.z, a.z, b2.z); c.w = fmaf(hv.w, a.w, b2.w);
    float4 z;
    z.x = fmaf(acc.x, inv, c.x); z.y = fmaf(acc.y, inv, c.y);
    z.z = fmaf(acc.z, inv, c.z); z.w = fmaf(acc.w, inv, c.w);
    ((float4*)g_t)[(size_t)gw*32 + lane] = z;

    float4 p;
    if (FIRST) {
        p = c;
    } else {
        p = ((float4*)g_pool)[(size_t)gw*32 + lane];
        p.x += c.x; p.y += c.y; p.z += c.z; p.w += c.w;
    }
    ((float4*)g_pool)[(size_t)gw*32 + lane] = p;

    atomicAdd(&sp[lane*4 + 0], c.x);
    atomicAdd(&sp[lane*4 + 1], c.y);
    atomicAdd(&sp[lane*4 + 2], c.z);
    atomicAdd(&sp[lane*4 + 3], c.w);
    __syncthreads();
    if (tid < H) {
        int b = blockIdx.x >> 7;   // 128 blocks per batch (8 rows/block)
        atomicAdd(&g_gp[b*H + tid], sp[tid] * (1.0f/NN));
    }
}

// ------------------- weight prep: split bf16, W^T [n][k] ---------------------
__global__ void wprep(const float* __restrict__ gin0_w2, const float* __restrict__ gin_w1,
                      const float* __restrict__ gin_w2, const float* __restrict__ pol0_w1,
                      const float* __restrict__ pol0_w2, const float* __restrict__ pol_w1,
                      const float* __restrict__ pol_w2) {
    int mat = blockIdx.y;
    const float* W;
    if      (mat == 0)  W = gin0_w2;
    else if (mat < 4)   W = gin_w1 + (size_t)(mat-1)*H*H;
    else if (mat < 7)   W = gin_w2 + (size_t)(mat-4)*H*H;
    else if (mat == 7)  W = pol0_w1;                    // first 128 rows
    else if (mat == 8)  W = pol0_w2;
    else if (mat < 11)  W = pol_w1 + (size_t)(mat-9)*H*H;
    else                W = pol_w2 + (size_t)(mat-11)*H*H;
    int idx = blockIdx.x*256 + threadIdx.x;             // 0..16383
    int n = idx >> 7, k = idx & 127;
    float el = W[(size_t)k*H + n];                      // B[n][k] = W[k][n]
    __nv_bfloat16 hb = __float2bfloat16(el);
    __nv_bfloat16 lb = __float2bfloat16(el - __bfloat162float(hb));
    unsigned short* base = g_wt + (size_t)mat*32768;
    base[idx]         = *(unsigned short*)&hb;
    base[16384 + idx] = *(unsigned short*)&lb;
}

// ------------------- HMMA GEMM: C[N,128] = epi(A@W + bias) -------------------
// split-bf16: C = Ahi*Bhi + Ahi*Blo + Alo*Bhi  (fp32 accum)
// 256 threads, 8 warps = 4M x 2N over a 128x128 tile (R9 core).
// EPI: 0 none, 1 relu.  STATS: column sum/sumsq into stats buffer (for BN).
#define BSTRIDE 136
#define SM_GEMM (2*128*BSTRIDE*2 + 512 + 1024)

template<int EPI, int STATS>
__global__ __launch_bounds__(256) void gemm_tc(
    const float* __restrict__ A, const float* __restrict__ bias,
    const unsigned short* __restrict__ Bt, float* __restrict__ C,
    float* __restrict__ stats)
{
    extern __shared__ __align__(16) char smem[];
    __nv_bfloat16* sBhi = (__nv_bfloat16*)smem;
    __nv_bfloat16* sBlo = sBhi + 128*BSTRIDE;
    float* sBias = (float*)(sBlo + 128*BSTRIDE);
    float* sSum  = sBias + 128;
    float* sSq   = sSum + 128;

    int tid = threadIdx.x;
    int wid = tid >> 5, lane = tid & 31;
    int wm = wid & 3, wn = wid >> 2;       // 4 M-warps x 2 N-warps
    int m0 = blockIdx.x * 128;

    if (tid < 128) {
        sBias[tid] = bias[tid];
        if (STATS) { sSum[tid] = 0.f; sSq[tid] = 0.f; }
    }
    {
        const uint4* Bg = (const uint4*)Bt;   // 4096 uint4 (hi 2048, lo 2048)
#pragma unroll
        for (int i = tid; i < 4096; i += 256) {
            int half = i >> 11;
            int j = i & 2047;
            int row = j >> 4, c = j & 15;
            __nv_bfloat16* d = (half ? sBlo : sBhi) + row*BSTRIDE + c*8;
            *(uint4*)d = Bg[i];
        }
    }
    __syncthreads();

    float acc[2][8][4];
#pragma unroll
    for (int mt = 0; mt < 2; mt++)
#pragma unroll
        for (int nt = 0; nt < 8; nt++)
#pragma unroll
            for (int q = 0; q < 4; q++) acc[mt][nt][q] = 0.f;

    int rbase = m0 + wm*32 + (lane >> 2);
    int cbase = (lane & 3)*2;
    int g  = lane >> 3, lr = lane & 7;
    const __nv_bfloat16* lbase = (g & 2) ? sBlo : sBhi;
    int kofs = (g & 1)*8;

#pragma unroll
    for (int k = 0; k < 8; k++) {
        int k0 = k*16;
        uint32_t ahi[2][4], alo[2][4];
#pragma unroll
        for (int mt = 0; mt < 2; mt++) {
            const float* Ar0 = A + (size_t)(rbase + mt*16)*H + k0 + cbase;
            const float* Ar1 = Ar0 + 8*H;
            split2(*(const float2*)Ar0,       ahi[mt][0], alo[mt][0]);
            split2(*(const float2*)Ar1,       ahi[mt][1], alo[mt][1]);
            split2(*(const float2*)(Ar0 + 8), ahi[mt][2], alo[mt][2]);
            split2(*(const float2*)(Ar1 + 8), ahi[mt][3], alo[mt][3]);
        }
#pragma unroll
        for (int nt = 0; nt < 8; nt++) {
            int n0 = wn*64 + nt*8;
            uint32_t addr = smem_u32(lbase + (size_t)(n0 + lr)*BSTRIDE + k0 + kofs);
            uint32_t bh0, bh1, bl0, bl1;
            ldsm_x4(bh0, bh1, bl0, bl1, addr);
#pragma unroll
            for (int mt = 0; mt < 2; mt++) {
                mma16816(acc[mt][nt], ahi[mt], bh0, bh1);
                mma16816(acc[mt][nt], ahi[mt], bl0, bl1);
                mma16816(acc[mt][nt], alo[mt], bh0, bh1);
            }
        }
    }

    float s0[8], s1[8], q0[8], q1[8];
    if (STATS) {
#pragma unroll
        for (int nt = 0; nt < 8; nt++) { s0[nt]=0.f; s1[nt]=0.f; q0[nt]=0.f; q1[nt]=0.f; }
    }
#pragma unroll
    for (int mt = 0; mt < 2; mt++) {
        int r0 = m0 + wm*32 + mt*16 + (lane >> 2);
#pragma unroll
        for (int nt = 0; nt < 8; nt++) {
            int col = wn*64 + nt*8 + (lane & 3)*2;
            float bx = sBias[col], by = sBias[col + 1];
            float v0 = acc[mt][nt][0] + bx, v1 = acc[mt][nt][1] + by;
            float v2 = acc[mt][nt][2] + bx, v3 = acc[mt][nt][3] + by;
            if (EPI == 1) {
                v0 = fmaxf(v0, 0.f); v1 = fmaxf(v1, 0.f);
                v2 = fmaxf(v2, 0.f); v3 = fmaxf(v3, 0.f);
            }
            if (STATS) {
                s0[nt] += v0 + v2;  s1[nt] += v1 + v3;
                q0[nt] = fmaf(v0, v0, fmaf(v2, v2, q0[nt]));
                q1[nt] = fmaf(v1, v1, fmaf(v3, v3, q1[nt]));
            }
            *(float2*)(C + (size_t)r0*H + col)       = make_float2(v0, v1);
            *(float2*)(C + (size_t)(r0 + 8)*H + col) = make_float2(v2, v3);
        }
    }
    if (STATS) {
#pragma unroll
        for (int nt = 0; nt < 8; nt++) {
#pragma unroll
            for (int off = 4; off < 32; off <<= 1) {
                s0[nt] += __shfl_xor_sync(0xffffffffu, s0[nt], off);
                s1[nt] += __shfl_xor_sync(0xffffffffu, s1[nt], off);
                q0[nt] += __shfl_xor_sync(0xffffffffu, q0[nt], off);
                q1[nt] += __shfl_xor_sync(0xffffffffu, q1[nt], off);
            }
            if (lane < 4) {
                int col = wn*64 + nt*8 + lane*2;
                atomicAdd(&sSum[col],     s0[nt]);
                atomicAdd(&sSum[col + 1], s1[nt]);
                atomicAdd(&sSq[col],      q0[nt]);
                atomicAdd(&sSq[col + 1],  q1[nt]);
            }
        }
        __syncthreads();
        if (tid < 128) {
            atomicAdd(&stats[tid],     sSum[tid]);
            atomicAdd(&stats[H + tid], sSq[tid]);
        }
    }
}

// ---------- fused GIN pair: raw = relu(relu(z@W1+b1)@W2+b2), + stats ---------
// GEMM1: A (z) from global registers (R9 path), B = sW1.  t -> smem bf16 hi/lo.
// GEMM2: A (t) from smem via ldmatrix, B = sW2.  raw -> global + BN stats.
#define SM_FUSE (3*(2*128*BSTRIDE*2) + 2048)

__global__ __launch_bounds__(256) void gin_fused(
    const float* __restrict__ A, const float* __restrict__ b1,
    const float* __restrict__ b2,
    const unsigned short* __restrict__ W1, const unsigned short* __restrict__ W2,
    float* __restrict__ C, float* __restrict__ stats)
{
    extern __shared__ __align__(16) char smem[];
    __nv_bfloat16* sW1hi = (__nv_bfloat16*)smem;
    __nv_bfloat16* sW1lo = sW1hi + 128*BSTRIDE;
    __nv_bfloat16* sW2hi = sW1lo + 128*BSTRIDE;
    __nv_bfloat16* sW2lo = sW2hi + 128*BSTRIDE;
    __nv_bfloat16* sThi  = sW2lo + 128*BSTRIDE;
    __nv_bfloat16* sTlo  = sThi  + 128*BSTRIDE;
    float* sB1   = (float*)(sTlo + 128*BSTRIDE);
    float* sB2   = sB1 + 128;
    float* sSum  = sB2 + 128;
    float* sSq   = sSum + 128;

    int tid = threadIdx.x;
    int wid = tid >> 5, lane = tid & 31;
    int wm = wid & 3, wn = wid >> 2;       // 4 M-warps x 2 N-warps
    int m0 = blockIdx.x * 128;

    if (tid < 128) {
        sB1[tid] = b1[tid];
        sB2[tid] = b2[tid];
        sSum[tid] = 0.f; sSq[tid] = 0.f;
    }
    // load both weight images
    {
        const uint4* B1g = (const uint4*)W1;
        const uint4* B2g = (const uint4*)W2;
#pragma unroll
        for (int i = tid; i < 4096; i += 256) {
            int half = i >> 11;
            int j = i & 2047;
            int row = j >> 4, c = j & 15;
            *(uint4*)((half ? sW1lo : sW1hi) + row*BSTRIDE + c*8) = B1g[i];
            *(uint4*)((half ? sW2lo : sW2hi) + row*BSTRIDE + c*8) = B2g[i];
        }
    }
    __syncthreads();

    int g  = lane >> 3, lr = lane & 7;
    int kofs = (g & 1)*8;

    // ---------------- GEMM1: t = relu(z @ W1 + b1) -> smem ----------------
    {
        float acc[2][8][4];
#pragma unroll
        for (int mt = 0; mt < 2; mt++)
#pragma unroll
            for (int nt = 0; nt < 8; nt++)
#pragma unroll
                for (int q = 0; q < 4; q++) acc[mt][nt][q] = 0.f;

        int rbase = m0 + wm*32 + (lane >> 2);
        int cbase = (lane & 3)*2;
        const __nv_bfloat16* lbase = (g & 2) ? sW1lo : sW1hi;

#pragma unroll
        for (int k = 0; k < 8; k++) {
            int k0 = k*16;
            uint32_t ahi[2][4], alo[2][4];
#pragma unroll
            for (int mt = 0; mt < 2; mt++) {
                const float* Ar0 = A + (size_t)(rbase + mt*16)*H + k0 + cbase;
                const float* Ar1 = Ar0 + 8*H;
                split2(*(const float2*)Ar0,       ahi[mt][0], alo[mt][0]);
                split2(*(const float2*)Ar1,       ahi[mt][1], alo[mt][1]);
                split2(*(const float2*)(Ar0 + 8), ahi[mt][2], alo[mt][2]);
                split2(*(const float2*)(Ar1 + 8), ahi[mt][3], alo[mt][3]);
            }
#pragma unroll
            for (int nt = 0; nt < 8; nt++) {
                int n0 = wn*64 + nt*8;
                uint32_t addr = smem_u32(lbase + (size_t)(n0 + lr)*BSTRIDE + k0 + kofs);
                uint32_t bh0, bh1, bl0, bl1;
                ldsm_x4(bh0, bh1, bl0, bl1, addr);
#pragma unroll
                for (int mt = 0; mt < 2; mt++) {
                    mma16816(acc[mt][nt], ahi[mt], bh0, bh1);
                    mma16816(acc[mt][nt], ahi[mt], bl0, bl1);
                    mma16816(acc[mt][nt], alo[mt], bh0, bh1);
                }
            }
        }

        // epilogue: bias + relu, split once, store t to smem (bf16x2 words)
#pragma unroll
        for (int mt = 0; mt < 2; mt++) {
            int rl = wm*32 + mt*16 + (lane >> 2);
#pragma unroll
            for (int nt = 0; nt < 8; nt++) {
                int col = wn*64 + nt*8 + (lane & 3)*2;
                float bx = sB1[col], by = sB1[col + 1];
                float v0 = fmaxf(acc[mt][nt][0] + bx, 0.f);
                float v1 = fmaxf(acc[mt][nt][1] + by, 0.f);
                float v2 = fmaxf(acc[mt][nt][2] + bx, 0.f);
                float v3 = fmaxf(acc[mt][nt][3] + by, 0.f);
                uint32_t h01, l01, h23, l23;
                split2(make_float2(v0, v1), h01, l01);
                split2(make_float2(v2, v3), h23, l23);
                *(uint32_t*)(sThi + rl*BSTRIDE + col)       = h01;
                *(uint32_t*)(sTlo + rl*BSTRIDE + col)       = l01;
                *(uint32_t*)(sThi + (rl + 8)*BSTRIDE + col) = h23;
                *(uint32_t*)(sTlo + (rl + 8)*BSTRIDE + col) = l23;
            }
        }
    }
    __syncthreads();

    // ---------------- GEMM2: raw = relu(t @ W2 + b2) -> global + stats -------
    {
        float acc[2][8][4];
#pragma unroll
        for (int mt = 0; mt < 2; mt++)
#pragma unroll
            for (int nt = 0; nt < 8; nt++)
#pragma unroll
                for (int q = 0; q < 4; q++) acc[mt][nt][q] = 0.f;

        const __nv_bfloat16* lbase = (g & 2) ? sW2lo : sW2hi;
        int arow  = wm*32 + (lane & 15);
        int acolh = (lane >> 4) * 8;

#pragma unroll
        for (int k = 0; k < 8; k++) {
            int k0 = k*16;
            uint32_t ahi[2][4], alo[2][4];
#pragma unroll
            for (int mt = 0; mt < 2; mt++) {
                uint32_t ah = smem_u32(sThi + (size_t)(arow + mt*16)*BSTRIDE + k0 + acolh);
                uint32_t al = smem_u32(sTlo + (size_t)(arow + mt*16)*BSTRIDE + k0 + acolh);
                ldsm_x4(ahi[mt][0], ahi[mt][1], ahi[mt][2], ahi[mt][3], ah);
                ldsm_x4(alo[mt][0], alo[mt][1], alo[mt][2], alo[mt][3], al);
            }
#pragma unroll
            for (int nt = 0; nt < 8; nt++) {
                int n0 = wn*64 + nt*8;
                uint32_t addr = smem_u32(lbase + (size_t)(n0 + lr)*BSTRIDE + k0 + kofs);
                uint32_t bh0, bh1, bl0, bl1;
                ldsm_x4(bh0, bh1, bl0, bl1, addr);
#pragma unroll
                for (int mt = 0; mt < 2; mt++) {
                    mma16816(acc[mt][nt], ahi[mt], bh0, bh1);
                    mma16816(acc[mt][nt], ahi[mt], bl0, bl1);
                    mma16816(acc[mt][nt], alo[mt], bh0, bh1);
                }
            }
        }

        float s0[8], s1[8], q0[8], q1[8];
#pragma unroll
        for (int nt = 0; nt < 8; nt++) { s0[nt]=0.f; s1[nt]=0.f; q0[nt]=0.f; q1[nt]=0.f; }
#pragma unroll
        for (int mt = 0; mt < 2; mt++) {
            int r0 = m0 + wm*32 + mt*16 + (lane >> 2);
#pragma unroll
            for (int nt = 0; nt < 8; nt++) {
                int col = wn*64 + nt*8 + (lane & 3)*2;
                float bx = sB2[col], by = sB2[col + 1];
                float v0 = fmaxf(acc[mt][nt][0] + bx, 0.f);
                float v1 = fmaxf(acc[mt][nt][1] + by, 0.f);
                float v2 = fmaxf(acc[mt][nt][2] + bx, 0.f);
                float v3 = fmaxf(acc[mt][nt][3] + by, 0.f);
                s0[nt] += v0 + v2;  s1[nt] += v1 + v3;
                q0[nt] = fmaf(v0, v0, fmaf(v2, v2, q0[nt]));
                q1[nt] = fmaf(v1, v1, fmaf(v3, v3, q1[nt]));
                *(float2*)(C + (size_t)r0*H + col)       = make_float2(v0, v1);
                *(float2*)(C + (size_t)(r0 + 8)*H + col) = make_float2(v2, v3);
            }
        }
#pragma unroll
        for (int nt = 0; nt < 8; nt++) {
#pragma unroll
            for (int off = 4; off < 32; off <<= 1) {
                s0[nt] += __shfl_xor_sync(0xffffffffu, s0[nt], off);
                s1[nt] += __shfl_xor_sync(0xffffffffu, s1[nt], off);
                q0[nt] += __shfl_xor_sync(0xffffffffu, q0[nt], off);
                q1[nt] += __shfl_xor_sync(0xffffffffu, q1[nt], off);
            }
            if (lane < 4) {
                int col = wn*64 + nt*8 + lane*2;
                atomicAdd(&sSum[col],     s0[nt]);
                atomicAdd(&sSum[col + 1], s1[nt]);
                atomicAdd(&sSq[col],      q0[nt]);
                atomicAdd(&sSq[col + 1],  q1[nt]);
            }
        }
        __syncthreads();
        if (tid < 128) {
            atomicAdd(&stats[tid],     sSum[tid]);
            atomicAdd(&stats[H + tid], sSq[tid]);
        }
    }
}

// ---------------- fused 6-layer policy MLP on compact rows -------------------
#define PZSTRIDE 132
#define SM_POL (2*128*BSTRIDE*2 + 32*PZSTRIDE*4 + 512)

__global__ __launch_bounds__(256) void policy_fused(
    const unsigned short* __restrict__ wt,
    const float* __restrict__ pol0_b2, const float* __restrict__ pol_b1,
    const float* __restrict__ pol_b2)
{
    extern __shared__ __align__(16) char smem[];
    __nv_bfloat16* sBhi = (__nv_bfloat16*)smem;
    __nv_bfloat16* sBlo = sBhi + 128*BSTRIDE;
    float* sZ    = (float*)(sBlo + 128*BSTRIDE);
    float* sBias = sZ + 32*PZSTRIDE;

    int tid = threadIdx.x;
    int wid = tid >> 5, lane = tid & 31;
    int wm = wid & 1, wn = wid >> 1;       // 2 M-warps(16) x 4 N-warps(32)
    int r0 = blockIdx.x * 32;
    int b  = blockIdx.x >> 2;

    for (int i = tid; i < 32*32; i += 256) {
        int row = i >> 5, c4 = i & 31;
        float4 v = ((const float4*)g_t)[(size_t)(r0 + row)*32 + c4];
        *(float4*)&sZ[row*PZSTRIDE + c4*4] = v;
    }

    const int mats[6] = {7, 8, 9, 11, 10, 12};
    int g  = lane >> 3, lr = lane & 7;
    const __nv_bfloat16* lbase = (g & 2) ? sBlo : sBhi;
    int kofs = (g & 1)*8;
    int arow = wm*16 + (lane >> 2);
    int acol = (lane & 3)*2;

#pragma unroll 1
    for (int l = 0; l < 6; l++) {
        __syncthreads();
        const uint4* Bg = (const uint4*)(wt + (size_t)mats[l]*32768);
#pragma unroll
        for (int i = tid; i < 4096; i += 256) {
            int half = i >> 11;
            int j = i & 2047;
            int row = j >> 4, c = j & 15;
            __nv_bfloat16* d = (half ? sBlo : sBhi) + row*BSTRIDE + c*8;
            *(uint4*)d = Bg[i];
        }
        if (tid < 128) {
            const float* bp;
            if      (l == 0) bp = g_gb + (size_t)b*H;
            else if (l == 1) bp = pol0_b2;
            else if (l == 2) bp = pol_b1;
            else if (l == 3) bp = pol_b2;
            else if (l == 4) bp = pol_b1 + H;
            else             bp = pol_b2 + H;
            sBias[tid] = bp[tid];
        }
        __syncthreads();

        float acc[4][4];
#pragma unroll
        for (int nt = 0; nt < 4; nt++)
#pragma unroll
            for (int q = 0; q < 4; q++) acc[nt][q] = 0.f;

#pragma unroll
        for (int k = 0; k < 8; k++) {
            int k0 = k*16;
            uint32_t ahi[4], alo[4];
            split2(*(const float2*)&sZ[arow*PZSTRIDE + k0 + acol],           ahi[0], alo[0]);
            split2(*(const float2*)&sZ[(arow + 8)*PZSTRIDE + k0 + acol],     ahi[1], alo[1]);
            split2(*(const float2*)&sZ[arow*PZSTRIDE + k0 + acol + 8],       ahi[2], alo[2]);
            split2(*(const float2*)&sZ[(arow + 8)*PZSTRIDE + k0 + acol + 8], ahi[3], alo[3]);
#pragma unroll
            for (int nt = 0; nt < 4; nt++) {
                int n0 = wn*32 + nt*8;
                uint32_t addr = smem_u32(lbase + (size_t)(n0 + lr)*BSTRIDE + k0 + kofs);
                uint32_t bh0, bh1, bl0, bl1;
                ldsm_x4(bh0, bh1, bl0, bl1, addr);
                mma16816(acc[nt], ahi, bh0, bh1);
                mma16816(acc[nt], ahi, bl0, bl1);
                mma16816(acc[nt], alo, bh0, bh1);
            }
        }
        __syncthreads();

        int ro = wm*16 + (lane >> 2);
#pragma unroll
        for (int nt = 0; nt < 4; nt++) {
            int col = wn*32 + nt*8 + (lane & 3)*2;
            float bx = sBias[col], by = sBias[col + 1];
            float v0 = acc[nt][0] + bx, v1 = acc[nt][1] + by;
            float v2 = acc[nt][2] + bx, v3 = acc[nt][3] + by;
            if ((l & 1) == 0) {
                v0 = tanhf(v0); v1 = tanhf(v1);
                v2 = tanhf(v2); v3 = tanhf(v3);
            }
            *(float2*)&sZ[ro*PZSTRIDE + col]       = make_float2(v0, v1);
            *(float2*)&sZ[(ro + 8)*PZSTRIDE + col] = make_float2(v2, v3);
        }
    }
    __syncthreads();

    for (int i = tid; i < 32*32; i += 256) {
        int row = i >> 5, c4 = i & 31;
        ((float4*)g_t)[(size_t)(r0 + row)*32 + c4] = *(float4*)&sZ[row*PZSTRIDE + c4*4];
    }
}

// layer-0 first linear: K = 8, z-fold, relu.  out -> g_t
__global__ __launch_bounds__(256) void gemm_l0(
    const float* __restrict__ x, const float* __restrict__ w1,
    const float* __restrict__ b1)
{
    __shared__ float sW[INF_DIM*H];
    __shared__ float sB[H];
    int tid = threadIdx.x;
    for (int i = tid; i < INF_DIM*H; i += 256) sW[i] = w1[i];
    if (tid < H) sB[tid] = b1[tid];
    __syncthreads();

    int t   = blockIdx.x*256 + tid;
    int row = t >> 5, cg = t & 31;
    float id = 1.f / fmaxf((float)g_cnt[row], 1.f);
    const float4* x4 = (const float4*)x;
    const float4* g4 = (const float4*)g_agg;
    float4 a0 = x4[(size_t)row*2],   a1 = x4[(size_t)row*2 + 1];
    float4 q0 = g4[(size_t)row*2],   q1 = g4[(size_t)row*2 + 1];
    float z[8] = { fmaf(q0.x,id,a0.x), fmaf(q0.y,id,a0.y), fmaf(q0.z,id,a0.z), fmaf(q0.w,id,a0.w),
                   fmaf(q1.x,id,a1.x), fmaf(q1.y,id,a1.y), fmaf(q1.z,id,a1.z), fmaf(q1.w,id,a1.w) };
    const float4* sW4 = (const float4*)sW;
    float4 acc = ((const float4*)sB)[cg];
#pragma unroll
    for (int k = 0; k < 8; k++) {
        float4 w = sW4[k*32 + cg];
        acc.x = fmaf(z[k], w.x, acc.x); acc.y = fmaf(z[k], w.y, acc.y);
        acc.z = fmaf(z[k], w.z, acc.z); acc.w = fmaf(z[k], w.w, acc.w);
    }
    acc.x = fmaxf(acc.x, 0.f); acc.y = fmaxf(acc.y, 0.f);
    acc.z = fmaxf(acc.z, 0.f); acc.w = fmaxf(acc.w, 0.f);
    ((float4*)g_t)[(size_t)row*32 + cg] = acc;
}

// ------------------------------ batch norm (final layer) ----------------------
template<int FIRST, int STORE>
__global__ __launch_bounds__(256) void bn_norm(
    const float* __restrict__ r, const float* __restrict__ stats,
    const float* __restrict__ gamma, const float* __restrict__ beta)
{
    __shared__ float sp[H];
    int tid = threadIdx.x;
    if (tid < H) sp[tid] = 0.f;
    __syncthreads();

    int idx = blockIdx.x*256 + tid;   // NTOT*32 float4s
    int cg  = idx & 31;
    float4 v  = ((const float4*)r)[idx];
    float4 s4 = ((const float4*)stats)[cg];
    float4 w4 = ((const float4*)(stats + H))[cg];
    const float invN = 1.0f/NTOT;
    float4 mu, iv;
    mu.x = s4.x*invN; mu.y = s4.y*invN; mu.z = s4.z*invN; mu.w = s4.w*invN;
    iv.x = rsqrtf(fmaf(-mu.x, mu.x, w4.x*invN) + 1e-5f);
    iv.y = rsqrtf(fmaf(-mu.y, mu.y, w4.y*invN) + 1e-5f);
    iv.z = rsqrtf(fmaf(-mu.z, mu.z, w4.z*invN) + 1e-5f);
    iv.w = rsqrtf(fmaf(-mu.w, mu.w, w4.w*invN) + 1e-5f);
    float4 ga = ((const float4*)gamma)[cg];
    float4 be = ((const float4*)beta)[cg];
    float4 c;
    c.x = fmaf((v.x - mu.x)*iv.x, ga.x, be.x);
    c.y = fmaf((v.y - mu.y)*iv.y, ga.y, be.y);
    c.z = fmaf((v.z - mu.z)*iv.z, ga.z, be.z);
    c.w = fmaf((v.w - mu.w)*iv.w, ga.w, be.w);
    if (STORE) ((float4*)g_h)[idx] = c;
    if (FIRST) {
        ((float4*)g_pool)[idx] = c;
    } else {
        float4 p = ((float4*)g_pool)[idx];
        p.x += c.x; p.y += c.y; p.z += c.z; p.w += c.w;
        ((float4*)g_pool)[idx] = p;
    }
    atomicAdd(&sp[cg*4 + 0], c.x);
    atomicAdd(&sp[cg*4 + 1], c.y);
    atomicAdd(&sp[cg*4 + 2], c.z);
    atomicAdd(&sp[cg*4 + 3], c.w);
    __syncthreads();
    if (tid < H) {
        int b = blockIdx.x >> 7;   // 128 blocks per batch (8 rows/block)
        atomicAdd(&g_gp[b*H + tid], sp[tid] * (1.0f/NN));
    }
}

// per-batch policy bias: gb[b] = gpool[b] @ pol0_w1[128:256,:] + pol0_b1
__global__ void gb_kernel(const float* __restrict__ w1, const float* __restrict__ b1) {
    int b = blockIdx.x, n = threadIdx.x;
    __shared__ float sg[H];
    sg[n] = g_gp[b*H + n];
    __syncthreads();
    float acc = b1[n];
#pragma unroll 8
    for (int k = 0; k < H; k++) acc = fmaf(sg[k], w1[(size_t)(H + k)*H + n], acc);
    g_gb[b*H + n] = acc;
}

// ------- compact policy rows: slot b*128+j <- pool[mask row or col row] ------
__global__ __launch_bounds__(256) void gather_pol(
    const int* __restrict__ mrows, const int* __restrict__ mcols)
{
    int s    = (blockIdx.x*256 + threadIdx.x) >> 5;   // 0..NPOL-1
    int lane = threadIdx.x & 31;
    int b = s >> 7, j = s & 127;
    int src = (j < FEAS) ? mrows[b*FEAS + j] : (b*NN + mcols[b*FEAS + j - FEAS]);
    float4 v = ((const float4*)g_pool)[(size_t)src*32 + lane];
    ((float4*)g_t)[(size_t)s*32 + lane] = v;
}

// ---------------------- final: masked score + softmax ------------------------
__global__ void final_softmax(const float* __restrict__ zc,
                              const int* __restrict__ mrows,
                              const int* __restrict__ mcols,
                              float* __restrict__ out)
{
    __shared__ int   srow[FEAS], scol[FEAS], sdup[FEAS];
    __shared__ float ss[FEAS];
    __shared__ float smx, ssum;
    int b = blockIdx.x, tid = threadIdx.x;
    if (tid < FEAS) {
        srow[tid] = mrows[b*FEAS + tid];
        scol[tid] = mcols[b*FEAS + tid];
    }
    __syncthreads();
    int lane = tid & 31, w = tid >> 5;
    for (int j = w; j < FEAS; j += 8) {
        const float* zr = zc + (size_t)(b*128 + j)*H;
        const float* zl = zc + (size_t)(b*128 + FEAS + j)*H;
        float s = 0.f;
        for (int k = lane; k < H; k += 32) s = fmaf(zr[k], zl[k], s);
#pragma unroll
        for (int o = 16; o; o >>= 1) s += __shfl_xor_sync(0xffffffffu, s, o);
        if (lane == 0) ss[j] = s;
    }
    __syncthreads();
    if (tid < FEAS) {
        int dup = 0;
        for (int k = 0; k < tid; k++)
            if (srow[k] == srow[tid] && scol[k] == scol[tid]) dup = 1;
        sdup[tid] = dup;
    }
    __syncthreads();
    if (tid == 0) {
        float mx = -1e30f;
        for (int j = 0; j < FEAS; j++) if (!sdup[j] && ss[j] > mx) mx = ss[j];
        float sum = 0.f;
        for (int j = 0; j < FEAS; j++) if (!sdup[j]) sum += expf(ss[j] - mx);
        smx = mx; ssum = sum;
    }
    __syncthreads();
    if (tid < FEAS) {
        int rl = srow[tid] - b*NN;
        size_t o = (size_t)b*NN*NN + (size_t)rl*NN + scol[tid];
        out[o] = expf(ss[tid] - smx) / ssum;
    }
}

// ------------------------------- host driver ---------------------------------
extern "C" void kernel_launch(void* const* d_in, const int* in_sizes, int n_in,
                              void* d_out, int out_size)
{
    const float* x       = (const float*)d_in[0];
    const int*   ei      = (const int*)  d_in[1];
    const int*   mrows   = (const int*)  d_in[3];
    const int*   mcols   = (const int*)  d_in[4];
    const float* gin0_w1 = (const float*)d_in[5];
    const float* gin0_b1 = (const float*)d_in[6];
    const float* gin0_w2 = (const float*)d_in[7];
    const float* gin0_b2 = (const float*)d_in[8];
    const float* gin_w1  = (const float*)d_in[9];
    const float* gin_b1  = (const float*)d_in[10];
    const float* gin_w2  = (const float*)d_in[11];
    const float* gin_b2  = (const float*)d_in[12];
    const float* bn_g    = (const float*)d_in[13];
    const float* bn_b    = (const float*)d_in[14];
    const float* pol0_w1 = (const float*)d_in[15];
    const float* pol0_b1 = (const float*)d_in[16];
    const float* pol0_w2 = (const float*)d_in[17];
    const float* pol0_b2 = (const float*)d_in[18];
    const float* pol_w1  = (const float*)d_in[19];
    const float* pol_b1  = (const float*)d_in[20];
    const float* pol_w2  = (const float*)d_in[21];
    const float* pol_b2  = (const float*)d_in[22];
    float* out = (float*)d_out;

    const int* src = ei;
    const int* dst = ei + NE;

    float *p_h, *p_t, *p_agg, *p_pool, *p_stats;
    unsigned short* p_wt;
    cudaGetSymbolAddress((void**)&p_h,     g_h);
    cudaGetSymbolAddress((void**)&p_t,     g_t);
    cudaGetSymbolAddress((void**)&p_agg,   g_agg);
    cudaGetSymbolAddress((void**)&p_pool,  g_pool);
    cudaGetSymbolAddress((void**)&p_stats, g_stats);
    cudaGetSymbolAddress((void**)&p_wt,    g_wt);
    auto WT = [&](int m) { return p_wt + (size_t)m*32768; };
    auto ST = [&](int l) { return p_stats + (size_t)l*2*H; };

    cudaFuncSetAttribute(gemm_tc<1,1>, cudaFuncAttributeMaxDynamicSharedMemorySize, SM_GEMM);
    cudaFuncSetAttribute(gin_fused,    cudaFuncAttributeMaxDynamicSharedMemorySize, SM_FUSE);
    cudaFuncSetAttribute(policy_fused, cudaFuncAttributeMaxDynamicSharedMemorySize, SM_POL);

    cudaMemsetAsync(d_out, 0, (size_t)out_size * sizeof(float), 0);

    wprep<<<dim3(64, NMAT), 256>>>(gin0_w2, gin_w1, gin_w2, pol0_w1, pol0_w2, pol_w1, pol_w2);
    zero_misc<<<NTOT/256, 256>>>();
    deg_count<<<NE/256, 256>>>(dst);
    scan1<<<128, 256>>>();
    scan2<<<1, 128>>>();
    scan3<<<128, 256>>>();
    fill_csr<<<NE/256, 256>>>(src, dst);

    // ---------------- GIN layer 0 (IN=8): raw0 -> g_agg ----------------
    scatter8 <<<NE*2/256, 256>>>(x, src, dst);
    gemm_l0  <<<NTOT*32/256, 256>>>(x, gin0_w1, gin0_b1);
    gemm_tc<1,1><<<NTOT/128, 256, SM_GEMM>>>(p_t, gin0_b2, WT(0), p_agg, ST(0));

    // ---------------- GIN layers 1..3 (gather+BN, fused GEMM pair) -----------
    for (int l = 0; l < 3; l++) {
        if (l == 0)
            gather_bn<1><<<NTOT*32/256, 256>>>(p_agg, ST(0), bn_g, bn_b);
        else
            gather_bn<0><<<NTOT*32/256, 256>>>(p_agg, ST(l),
                                               bn_g + (size_t)l*H, bn_b + (size_t)l*H);
        gin_fused<<<NTOT/128, 256, SM_FUSE>>>(p_t, gin_b1 + l*H, gin_b2 + l*H,
                                              WT(1 + l), WT(4 + l), p_agg, ST(l + 1));
    }
    // final BN (layer 3): pool/gpool only
    bn_norm<0,0><<<NTOT*32/256, 256>>>(p_agg, ST(3), bn_g + (size_t)3*H, bn_b + (size_t)3*H);

    // ---------------- policy head: compact rows + fused 6-layer MLP ----------
    gb_kernel<<<BATCH, 128>>>(pol0_w1, pol0_b1);
    gather_pol<<<NPOL*32/256, 256>>>(mrows, mcols);   // g_pool -> g_t (compact)
    policy_fused<<<128, 256, SM_POL>>>(p_wt, pol0_b2, pol_b1, pol_b2);

    // ---------------- masked score + softmax ----------------
    final_softmax<<<BATCH, 256>>>(p_t, mrows, mcols, out);
}